// round 2
// baseline (speedup 1.0000x reference)
#include <cuda_runtime.h>
#include <math.h>

// Problem shape (fixed by the dataset)
#define BB 4
#define SS 4096
#define DD 256
#define HH 1024
#define SCALE 0.1767766952966369f   // (D / n_head)^-0.5 = 32^-0.5

// ---------------------------------------------------------------------------
// Scratch (no cudaMalloc allowed -> __device__ globals)
// ---------------------------------------------------------------------------
__device__ float g_scores[(size_t)BB * SS * SS];   // 268 MB
__device__ float g_a[(size_t)BB * SS * DD];        // 16 MB
__device__ float g_h[(size_t)BB * SS * DD];        // 16 MB
__device__ float g_f1[(size_t)BB * SS * HH];       // 67 MB
__device__ float g_f2[(size_t)BB * SS * DD];       // 16 MB

// ---------------------------------------------------------------------------
// GEMM NT: C[b] = scale * A[b] @ A[b]^T   (scores = x x^T)
// A: [S, D] row-major per batch.  Tile 64x64, 256 threads, 4x4 microtile.
// ---------------------------------------------------------------------------
__global__ void gemm_nt_scores(const float* __restrict__ x, float* __restrict__ out) {
    const int bz = blockIdx.z;
    const float* A = x + (size_t)bz * SS * DD;
    float* C = out + (size_t)bz * SS * SS;
    const int m0 = blockIdx.y * 64;
    const int n0 = blockIdx.x * 64;

    __shared__ float As[64][17];
    __shared__ float Bs[64][17];

    const int tid = threadIdx.x;
    const int tx = tid & 15;
    const int ty = tid >> 4;
    const int lr = tid >> 2;          // 0..63
    const int lc = (tid & 3) * 4;     // 0,4,8,12

    float acc[4][4] = {};

    for (int k0 = 0; k0 < DD; k0 += 16) {
        float4 av = *(const float4*)(A + (size_t)(m0 + lr) * DD + k0 + lc);
        As[lr][lc + 0] = av.x; As[lr][lc + 1] = av.y;
        As[lr][lc + 2] = av.z; As[lr][lc + 3] = av.w;
        float4 bv = *(const float4*)(A + (size_t)(n0 + lr) * DD + k0 + lc);
        Bs[lr][lc + 0] = bv.x; Bs[lr][lc + 1] = bv.y;
        Bs[lr][lc + 2] = bv.z; Bs[lr][lc + 3] = bv.w;
        __syncthreads();

        #pragma unroll
        for (int kk = 0; kk < 16; kk++) {
            float a[4], b[4];
            #pragma unroll
            for (int i = 0; i < 4; i++) a[i] = As[ty * 4 + i][kk];
            #pragma unroll
            for (int j = 0; j < 4; j++) b[j] = Bs[tx * 4 + j][kk];
            #pragma unroll
            for (int i = 0; i < 4; i++)
                #pragma unroll
                for (int j = 0; j < 4; j++)
                    acc[i][j] += a[i] * b[j];
        }
        __syncthreads();
    }

    #pragma unroll
    for (int i = 0; i < 4; i++)
        #pragma unroll
        for (int j = 0; j < 4; j++)
            C[(size_t)(m0 + ty * 4 + i) * SS + n0 + tx * 4 + j] = acc[i][j] * SCALE;
}

// ---------------------------------------------------------------------------
// GEMM NN (batched via z-strides): C = A @ B (+bias) (+relu)
// A: [M,K], B: [K,N], C: [M,N] row-major. Tile 64x64, 256 threads, 4x4.
// ---------------------------------------------------------------------------
__global__ void gemm_nn(const float* __restrict__ A, const float* __restrict__ Bm,
                        float* __restrict__ C, const float* __restrict__ bias,
                        int M, int N, int K, int relu,
                        size_t strideA, size_t strideB, size_t strideC) {
    const int bz = blockIdx.z;
    const float* Ab = A + strideA * bz;
    const float* Bb = Bm + strideB * bz;
    float* Cb = C + strideC * bz;
    const int m0 = blockIdx.y * 64;
    const int n0 = blockIdx.x * 64;

    __shared__ float As[64][17];
    __shared__ float Bs[16][64];

    const int tid = threadIdx.x;
    const int tx = tid & 15;
    const int ty = tid >> 4;
    const int lr = tid >> 2;          // 0..63 (A row)
    const int lc = (tid & 3) * 4;     // 0,4,8,12 (A col group)
    const int br = tid >> 4;          // 0..15 (B row)
    const int bc = (tid & 15) * 4;    // 0..60 (B col group)

    float acc[4][4] = {};

    for (int k0 = 0; k0 < K; k0 += 16) {
        float4 av = *(const float4*)(Ab + (size_t)(m0 + lr) * K + k0 + lc);
        As[lr][lc + 0] = av.x; As[lr][lc + 1] = av.y;
        As[lr][lc + 2] = av.z; As[lr][lc + 3] = av.w;
        float4 bv = *(const float4*)(Bb + (size_t)(k0 + br) * N + n0 + bc);
        *(float4*)&Bs[br][bc] = bv;
        __syncthreads();

        #pragma unroll
        for (int kk = 0; kk < 16; kk++) {
            float a[4];
            #pragma unroll
            for (int i = 0; i < 4; i++) a[i] = As[ty * 4 + i][kk];
            float4 b = *(const float4*)&Bs[kk][tx * 4];
            #pragma unroll
            for (int i = 0; i < 4; i++) {
                acc[i][0] += a[i] * b.x;
                acc[i][1] += a[i] * b.y;
                acc[i][2] += a[i] * b.z;
                acc[i][3] += a[i] * b.w;
            }
        }
        __syncthreads();
    }

    float bvx[4] = {0.f, 0.f, 0.f, 0.f};
    if (bias) {
        #pragma unroll
        for (int j = 0; j < 4; j++) bvx[j] = bias[n0 + tx * 4 + j];
    }
    #pragma unroll
    for (int i = 0; i < 4; i++)
        #pragma unroll
        for (int j = 0; j < 4; j++) {
            float v = acc[i][j] + bvx[j];
            if (relu) v = fmaxf(v, 0.0f);
            Cb[(size_t)(m0 + ty * 4 + i) * N + n0 + tx * 4 + j] = v;
        }
}

// ---------------------------------------------------------------------------
// Row softmax over the last dim (4096), in place. One 256-thread block per row.
// Row chunk held in registers (16 floats/thread): 1 read + 1 write of HBM.
// ---------------------------------------------------------------------------
__global__ void softmax_rows(float* __restrict__ sc) {
    const size_t row = blockIdx.x;
    float* p = sc + row * (size_t)SS;
    const int t = threadIdx.x;
    __shared__ float sm[8];

    float rv[16];
    float mx = -1e30f;
    #pragma unroll
    for (int i = 0; i < 16; i++) {
        rv[i] = p[t + 256 * i];
        mx = fmaxf(mx, rv[i]);
    }
    #pragma unroll
    for (int o = 16; o > 0; o >>= 1) mx = fmaxf(mx, __shfl_xor_sync(0xffffffffu, mx, o));
    if ((t & 31) == 0) sm[t >> 5] = mx;
    __syncthreads();
    if (t < 32) {
        float z = (t < 8) ? sm[t] : -1e30f;
        #pragma unroll
        for (int o = 4; o > 0; o >>= 1) z = fmaxf(z, __shfl_xor_sync(0xffffffffu, z, o));
        if (t == 0) sm[0] = z;
    }
    __syncthreads();
    mx = sm[0];
    __syncthreads();

    float s = 0.f;
    #pragma unroll
    for (int i = 0; i < 16; i++) {
        rv[i] = __expf(rv[i] - mx);
        s += rv[i];
    }
    #pragma unroll
    for (int o = 16; o > 0; o >>= 1) s += __shfl_xor_sync(0xffffffffu, s, o);
    if ((t & 31) == 0) sm[t >> 5] = s;
    __syncthreads();
    if (t < 32) {
        float z = (t < 8) ? sm[t] : 0.f;
        #pragma unroll
        for (int o = 4; o > 0; o >>= 1) z += __shfl_xor_sync(0xffffffffu, z, o);
        if (t == 0) sm[0] = z;
    }
    __syncthreads();
    const float inv = 1.0f / sm[0];
    #pragma unroll
    for (int i = 0; i < 16; i++) p[t + 256 * i] = rv[i] * inv;
}

// ---------------------------------------------------------------------------
// out = LayerNorm(a + r) * gamma + beta.  One 256-thread block per row (D=256).
// ---------------------------------------------------------------------------
__global__ void add_ln(const float* __restrict__ a, const float* __restrict__ r,
                       const float* __restrict__ g, const float* __restrict__ be,
                       float* __restrict__ out) {
    const size_t row = blockIdx.x;
    const int t = threadIdx.x;
    const size_t idx = row * DD + t;
    const float v = a[idx] + r[idx];
    __shared__ float sm[8];

    float s = v;
    #pragma unroll
    for (int o = 16; o > 0; o >>= 1) s += __shfl_xor_sync(0xffffffffu, s, o);
    if ((t & 31) == 0) sm[t >> 5] = s;
    __syncthreads();
    if (t < 32) {
        float z = (t < 8) ? sm[t] : 0.f;
        #pragma unroll
        for (int o = 4; o > 0; o >>= 1) z += __shfl_xor_sync(0xffffffffu, z, o);
        if (t == 0) sm[0] = z;
    }
    __syncthreads();
    const float mean = sm[0] * (1.0f / 256.0f);
    __syncthreads();

    const float d = v - mean;
    float q = d * d;
    #pragma unroll
    for (int o = 16; o > 0; o >>= 1) q += __shfl_xor_sync(0xffffffffu, q, o);
    if ((t & 31) == 0) sm[t >> 5] = q;
    __syncthreads();
    if (t < 32) {
        float z = (t < 8) ? sm[t] : 0.f;
        #pragma unroll
        for (int o = 4; o > 0; o >>= 1) z += __shfl_xor_sync(0xffffffffu, z, o);
        if (t == 0) sm[0] = z;
    }
    __syncthreads();
    const float var = sm[0] * (1.0f / 256.0f);
    out[idx] = d * rsqrtf(var + 1e-5f) * g[t] + be[t];
}

// ---------------------------------------------------------------------------
// Launch
// ---------------------------------------------------------------------------
extern "C" void kernel_launch(void* const* d_in, const int* in_sizes, int n_in,
                              void* d_out, int out_size) {
    const float* x      = (const float*)d_in[0];
    const float* gamma1 = (const float*)d_in[1];
    const float* beta1  = (const float*)d_in[2];
    const float* W1     = (const float*)d_in[3];
    const float* b1     = (const float*)d_in[4];
    const float* W2     = (const float*)d_in[5];
    const float* b2     = (const float*)d_in[6];
    const float* gamma2 = (const float*)d_in[7];
    const float* beta2  = (const float*)d_in[8];
    float* out = (float*)d_out;

    float *scores, *a, *h, *f1, *f2;
    cudaGetSymbolAddress((void**)&scores, g_scores);
    cudaGetSymbolAddress((void**)&a, g_a);
    cudaGetSymbolAddress((void**)&h, g_h);
    cudaGetSymbolAddress((void**)&f1, g_f1);
    cudaGetSymbolAddress((void**)&f2, g_f2);

    const int rows = BB * SS;  // 16384

    // 1) scores = scale * x x^T   [B,S,S]
    gemm_nt_scores<<<dim3(SS / 64, SS / 64, BB), 256>>>(x, scores);

    // 2) softmax over last dim, in place
    softmax_rows<<<rows, 256>>>(scores);

    // 3) a = P @ x   [B,S,D]  (batched)
    gemm_nn<<<dim3(DD / 64, SS / 64, BB), 256>>>(
        scores, x, a, nullptr, SS, DD, SS, 0,
        (size_t)SS * SS, (size_t)SS * DD, (size_t)SS * DD);

    // 4) h = LN(a + x)
    add_ln<<<rows, 256>>>(a, x, gamma1, beta1, h);

    // 5) f1 = relu(h @ W1 + b1)   [16384, 1024]
    gemm_nn<<<dim3(HH / 64, rows / 64, 1), 256>>>(
        h, W1, f1, b1, rows, HH, DD, 1, 0, 0, 0);

    // 6) f2 = f1 @ W2 + b2        [16384, 256]
    gemm_nn<<<dim3(DD / 64, rows / 64, 1), 256>>>(
        f1, W2, f2, b2, rows, DD, HH, 0, 0, 0, 0);

    // 7) out = LN(f2 + h)
    add_ln<<<rows, 256>>>(f2, h, gamma2, beta2, out);
}

// round 4
// speedup vs baseline: 3.1823x; 3.1823x over previous
#include <cuda_runtime.h>
#include <cuda_bf16.h>
#include <cstdint>
#include <math.h>

#define BB 4
#define SS 4096
#define DD 256
#define HH 1024
#define SCALE 0.1767766952966369f   // 32^-0.5

typedef __nv_bfloat16 bf16;

// ---------------------------------------------------------------------------
// Scratch (__device__ globals; no cudaMalloc allowed)
// ---------------------------------------------------------------------------
__device__ float g_scores[(size_t)BB * SS * SS];     // 268 MB
__device__ bf16  g_Phi[(size_t)BB * SS * SS];        // 134 MB
__device__ bf16  g_Plo[(size_t)BB * SS * SS];        // 134 MB
__device__ bf16  g_xhi[(size_t)BB * SS * DD];
__device__ bf16  g_xlo[(size_t)BB * SS * DD];
__device__ bf16  g_xThi[(size_t)BB * SS * DD];       // [B][D][S]
__device__ bf16  g_xTlo[(size_t)BB * SS * DD];
__device__ float g_a[(size_t)BB * SS * DD];
__device__ float g_h[(size_t)BB * SS * DD];
__device__ bf16  g_hhi[(size_t)BB * SS * DD];
__device__ bf16  g_hlo[(size_t)BB * SS * DD];
__device__ bf16  g_f1hi[(size_t)BB * SS * HH];
__device__ bf16  g_f1lo[(size_t)BB * SS * HH];
__device__ float g_f2[(size_t)BB * SS * DD];
__device__ bf16  g_w1thi[(size_t)HH * DD];           // W1^T [H,D]
__device__ bf16  g_w1tlo[(size_t)HH * DD];
__device__ bf16  g_w2thi[(size_t)DD * HH];           // W2^T [D,H]
__device__ bf16  g_w2tlo[(size_t)DD * HH];

// ---------------------------------------------------------------------------
// Helpers (baseline PTX only: cp.async, ldmatrix, mma.sync — all compute_103 OK)
// ---------------------------------------------------------------------------
__device__ __forceinline__ uint32_t smem_u32(const void* p) {
    uint32_t a;
    asm("{ .reg .u64 t; cvta.to.shared.u64 t, %1; cvt.u32.u64 %0, t; }" : "=r"(a) : "l"(p));
    return a;
}
__device__ __forceinline__ void cpa16(uint32_t d, const void* g) {
    asm volatile("cp.async.cg.shared.global [%0], [%1], 16;" :: "r"(d), "l"(g) : "memory");
}
__device__ __forceinline__ uint32_t swz(uint32_t off) { return off ^ ((off >> 3) & 0x70); }

__device__ __forceinline__ void ldsm4(uint32_t& r0, uint32_t& r1, uint32_t& r2, uint32_t& r3,
                                      uint32_t addr) {
    asm volatile("ldmatrix.sync.aligned.m8n8.x4.shared.b16 {%0,%1,%2,%3}, [%4];"
        : "=r"(r0), "=r"(r1), "=r"(r2), "=r"(r3) : "r"(addr));
}
__device__ __forceinline__ void mma_bf16(float* d, uint32_t a0, uint32_t a1, uint32_t a2,
                                         uint32_t a3, uint32_t b0, uint32_t b1) {
    asm volatile("mma.sync.aligned.m16n8k16.row.col.f32.bf16.bf16.f32 "
        "{%0,%1,%2,%3}, {%4,%5,%6,%7}, {%8,%9}, {%0,%1,%2,%3};"
        : "+f"(d[0]), "+f"(d[1]), "+f"(d[2]), "+f"(d[3])
        : "r"(a0), "r"(a1), "r"(a2), "r"(a3), "r"(b0), "r"(b1));
}

// ---------------------------------------------------------------------------
// Split-bf16 mma.sync GEMM: C[M,N] = A[M,K] * B[N,K]^T, fp32-emulated via
// Ahi*Bhi + Ahi*Blo + Alo*Bhi with fp32 accumulators.
// MODE 0: C fp32 = acc * SCALE       MODE 1: C fp32 = acc
// MODE 2: (Chi,Clo) bf16 = split(relu(acc + bias))
// MODE 3: C fp32 = acc + bias
// Block tile 128x128, K-tile 64, 8 warps (2x4), warp tile 64x32.
// ---------------------------------------------------------------------------
#define Bb 65536        // per-buffer smem bytes: Ahi|Alo|Bhi|Blo each 16KB
template <int MODE>
__global__ void __launch_bounds__(256, 1) gemm_mma(
    const bf16* __restrict__ Ahi_, const bf16* __restrict__ Alo_,
    const bf16* __restrict__ Bhi_, const bf16* __restrict__ Blo_,
    float* __restrict__ C, bf16* __restrict__ Chi, bf16* __restrict__ Clo,
    const float* __restrict__ bias,
    int M, int N, int K, size_t sA, size_t sB, size_t sC)
{
    extern __shared__ char smem[];
    const uint32_t sb = smem_u32(smem);
    const int tid = threadIdx.x, wid = tid >> 5, lane = tid & 31;
    const int bz = blockIdx.z;
    const int m0 = blockIdx.y * 128, n0 = blockIdx.x * 128;
    const bf16* Ahi = Ahi_ + sA * bz;
    const bf16* Alo = Alo_ + sA * bz;
    const bf16* Bhi = Bhi_ + sB * bz;
    const bf16* Blo = Blo_ + sB * bz;

    const int wm = wid & 1;       // 2 M-groups of 64
    const int wn = wid >> 1;      // 4 N-groups of 32

    const int a_row = lane & 15, a_kh = lane >> 4;
    const int b_roff = ((lane >> 4) & 1) * 8 + (lane & 7), b_kh = (lane >> 3) & 1;

    float acc[4][4][4];
    #pragma unroll
    for (int i = 0; i < 4; i++)
        #pragma unroll
        for (int j = 0; j < 4; j++)
            #pragma unroll
            for (int q = 0; q < 4; q++) acc[i][j][q] = 0.0f;

    const int KT = K >> 6;

    auto load_tile = [&](int kt) {
        const uint32_t tb = sb + (kt & 1) * Bb;
        const int k0 = kt << 6;
        #pragma unroll
        for (int t = 0; t < 4; t++) {
            int id = tid + t * 256;
            int row = id >> 3, ch = id & 7;
            uint32_t so = swz((uint32_t)(row * 128 + ch * 16));
            const size_t ga = (size_t)(m0 + row) * K + k0 + ch * 8;
            const size_t gb = (size_t)(n0 + row) * K + k0 + ch * 8;
            cpa16(tb + so,         Ahi + ga);
            cpa16(tb + 16384 + so, Alo + ga);
            cpa16(tb + 32768 + so, Bhi + gb);
            cpa16(tb + 49152 + so, Blo + gb);
        }
        asm volatile("cp.async.commit_group;" ::: "memory");
    };

    load_tile(0);

    for (int kt = 0; kt < KT; kt++) {
        if (kt + 1 < KT) {
            load_tile(kt + 1);
            asm volatile("cp.async.wait_group 1;" ::: "memory");
        } else {
            asm volatile("cp.async.wait_group 0;" ::: "memory");
        }
        __syncthreads();

        const uint32_t tb = sb + (kt & 1) * Bb;
        #pragma unroll
        for (int s = 0; s < 4; s++) {
            uint32_t ah[4][4], al[4][4];
            #pragma unroll
            for (int i = 0; i < 4; i++) {
                uint32_t off = swz((uint32_t)((wm * 64 + i * 16 + a_row) * 128 +
                                              (s * 2 + a_kh) * 16));
                ldsm4(ah[i][0], ah[i][1], ah[i][2], ah[i][3], tb + off);
                ldsm4(al[i][0], al[i][1], al[i][2], al[i][3], tb + 16384 + off);
            }
            uint32_t bh[4][2], bl[4][2];
            #pragma unroll
            for (int jj = 0; jj < 2; jj++) {
                uint32_t off = swz((uint32_t)((wn * 32 + jj * 16 + b_roff) * 128 +
                                              (s * 2 + b_kh) * 16));
                ldsm4(bh[2 * jj][0], bh[2 * jj][1], bh[2 * jj + 1][0], bh[2 * jj + 1][1],
                      tb + 32768 + off);
                ldsm4(bl[2 * jj][0], bl[2 * jj][1], bl[2 * jj + 1][0], bl[2 * jj + 1][1],
                      tb + 49152 + off);
            }
            #pragma unroll
            for (int i = 0; i < 4; i++)
                #pragma unroll
                for (int j = 0; j < 4; j++) {
                    mma_bf16(acc[i][j], ah[i][0], ah[i][1], ah[i][2], ah[i][3],
                             bh[j][0], bh[j][1]);
                    mma_bf16(acc[i][j], ah[i][0], ah[i][1], ah[i][2], ah[i][3],
                             bl[j][0], bl[j][1]);
                    mma_bf16(acc[i][j], al[i][0], al[i][1], al[i][2], al[i][3],
                             bh[j][0], bh[j][1]);
                }
        }
        __syncthreads();
    }

    // Epilogue: thread t owns rows g,g+8 (g=lane>>2), cols (lane&3)*2,+1 per tile
    const int g = lane >> 2, cq = (lane & 3) * 2;
    #pragma unroll
    for (int i = 0; i < 4; i++) {
        #pragma unroll
        for (int j = 0; j < 4; j++) {
            const int row = m0 + wm * 64 + i * 16 + g;
            const int col = n0 + wn * 32 + j * 8 + cq;
            float v0 = acc[i][j][0], v1 = acc[i][j][1];
            float v2 = acc[i][j][2], v3 = acc[i][j][3];
            if (MODE == 0) { v0 *= SCALE; v1 *= SCALE; v2 *= SCALE; v3 *= SCALE; }
            if (MODE == 2 || MODE == 3) {
                const float bv0 = bias[col], bv1 = bias[col + 1];
                v0 += bv0; v1 += bv1; v2 += bv0; v3 += bv1;
            }
            if (MODE == 2) {
                v0 = fmaxf(v0, 0.f); v1 = fmaxf(v1, 0.f);
                v2 = fmaxf(v2, 0.f); v3 = fmaxf(v3, 0.f);
                size_t i0 = sC * bz + (size_t)row * N + col;
                size_t i1 = sC * bz + (size_t)(row + 8) * N + col;
                bf16 h0 = __float2bfloat16(v0), h1 = __float2bfloat16(v1);
                bf16 h2 = __float2bfloat16(v2), h3 = __float2bfloat16(v3);
                *(__nv_bfloat162*)(Chi + i0) = {h0, h1};
                *(__nv_bfloat162*)(Chi + i1) = {h2, h3};
                *(__nv_bfloat162*)(Clo + i0) =
                    {__float2bfloat16(v0 - __bfloat162float(h0)),
                     __float2bfloat16(v1 - __bfloat162float(h1))};
                *(__nv_bfloat162*)(Clo + i1) =
                    {__float2bfloat16(v2 - __bfloat162float(h2)),
                     __float2bfloat16(v3 - __bfloat162float(h3))};
            } else {
                size_t i0 = sC * bz + (size_t)row * N + col;
                size_t i1 = sC * bz + (size_t)(row + 8) * N + col;
                *(float2*)(C + i0) = {v0, v1};
                *(float2*)(C + i1) = {v2, v3};
            }
        }
    }
}

// ---------------------------------------------------------------------------
// Elementwise / conversion kernels
// ---------------------------------------------------------------------------
__global__ void split_f32(const float* __restrict__ in, bf16* __restrict__ hi,
                          bf16* __restrict__ lo, size_t n) {
    size_t i = (size_t)blockIdx.x * blockDim.x + threadIdx.x;
    if (i < n) {
        float v = in[i];
        bf16 h = __float2bfloat16(v);
        hi[i] = h;
        lo[i] = __float2bfloat16(v - __bfloat162float(h));
    }
}

__global__ void transpose_split(const float* __restrict__ in, bf16* __restrict__ ohi,
                                bf16* __restrict__ olo, int R, int C,
                                size_t sIn, size_t sOut) {
    __shared__ float t[32][33];
    const int bz = blockIdx.z;
    const float* ip = in + sIn * bz;
    bf16* oh = ohi + sOut * bz;
    bf16* ol = olo + sOut * bz;
    int c = blockIdx.x * 32 + threadIdx.x;
    #pragma unroll
    for (int i = 0; i < 4; i++) {
        int r = blockIdx.y * 32 + threadIdx.y + i * 8;
        if (r < R && c < C) t[threadIdx.y + i * 8][threadIdx.x] = ip[(size_t)r * C + c];
    }
    __syncthreads();
    int rr = blockIdx.y * 32 + threadIdx.x;
    #pragma unroll
    for (int i = 0; i < 4; i++) {
        int cc = blockIdx.x * 32 + threadIdx.y + i * 8;
        if (rr < R && cc < C) {
            float v = t[threadIdx.x][threadIdx.y + i * 8];
            bf16 h = __float2bfloat16(v);
            size_t idx = (size_t)cc * R + rr;
            oh[idx] = h;
            ol[idx] = __float2bfloat16(v - __bfloat162float(h));
        }
    }
}

__global__ void softmax_rows(const float* __restrict__ sc, bf16* __restrict__ phi,
                             bf16* __restrict__ plo) {
    const size_t row = blockIdx.x;
    const float* p = sc + row * (size_t)SS;
    bf16* oh = phi + row * (size_t)SS;
    bf16* ol = plo + row * (size_t)SS;
    const int t = threadIdx.x;
    __shared__ float sm[8];

    float rv[16];
    float mx = -1e30f;
    #pragma unroll
    for (int i = 0; i < 16; i++) { rv[i] = p[t + 256 * i]; mx = fmaxf(mx, rv[i]); }
    #pragma unroll
    for (int o = 16; o > 0; o >>= 1) mx = fmaxf(mx, __shfl_xor_sync(0xffffffffu, mx, o));
    if ((t & 31) == 0) sm[t >> 5] = mx;
    __syncthreads();
    if (t < 32) {
        float z = (t < 8) ? sm[t] : -1e30f;
        #pragma unroll
        for (int o = 4; o > 0; o >>= 1) z = fmaxf(z, __shfl_xor_sync(0xffffffffu, z, o));
        if (t == 0) sm[0] = z;
    }
    __syncthreads();
    mx = sm[0];
    __syncthreads();

    float s = 0.f;
    #pragma unroll
    for (int i = 0; i < 16; i++) { rv[i] = __expf(rv[i] - mx); s += rv[i]; }
    #pragma unroll
    for (int o = 16; o > 0; o >>= 1) s += __shfl_xor_sync(0xffffffffu, s, o);
    if ((t & 31) == 0) sm[t >> 5] = s;
    __syncthreads();
    if (t < 32) {
        float z = (t < 8) ? sm[t] : 0.f;
        #pragma unroll
        for (int o = 4; o > 0; o >>= 1) z += __shfl_xor_sync(0xffffffffu, z, o);
        if (t == 0) sm[0] = z;
    }
    __syncthreads();
    const float inv = 1.0f / sm[0];
    #pragma unroll
    for (int i = 0; i < 16; i++) {
        float v = rv[i] * inv;
        bf16 h = __float2bfloat16(v);
        oh[t + 256 * i] = h;
        ol[t + 256 * i] = __float2bfloat16(v - __bfloat162float(h));
    }
}

__global__ void add_ln_split(const float* __restrict__ a, const float* __restrict__ r,
                             const float* __restrict__ g, const float* __restrict__ be,
                             float* __restrict__ out, bf16* __restrict__ ohi,
                             bf16* __restrict__ olo) {
    const size_t row = blockIdx.x;
    const int t = threadIdx.x;
    const size_t idx = row * DD + t;
    const float v = a[idx] + r[idx];
    __shared__ float sm[8];

    float s = v;
    #pragma unroll
    for (int o = 16; o > 0; o >>= 1) s += __shfl_xor_sync(0xffffffffu, s, o);
    if ((t & 31) == 0) sm[t >> 5] = s;
    __syncthreads();
    if (t < 32) {
        float z = (t < 8) ? sm[t] : 0.f;
        #pragma unroll
        for (int o = 4; o > 0; o >>= 1) z += __shfl_xor_sync(0xffffffffu, z, o);
        if (t == 0) sm[0] = z;
    }
    __syncthreads();
    const float mean = sm[0] * (1.0f / 256.0f);
    __syncthreads();

    const float d = v - mean;
    float q = d * d;
    #pragma unroll
    for (int o = 16; o > 0; o >>= 1) q += __shfl_xor_sync(0xffffffffu, q, o);
    if ((t & 31) == 0) sm[t >> 5] = q;
    __syncthreads();
    if (t < 32) {
        float z = (t < 8) ? sm[t] : 0.f;
        #pragma unroll
        for (int o = 4; o > 0; o >>= 1) z += __shfl_xor_sync(0xffffffffu, z, o);
        if (t == 0) sm[0] = z;
    }
    __syncthreads();
    const float var = sm[0] * (1.0f / 256.0f);
    const float res = d * rsqrtf(var + 1e-5f) * g[t] + be[t];
    out[idx] = res;
    if (ohi) {
        bf16 h = __float2bfloat16(res);
        ohi[idx] = h;
        olo[idx] = __float2bfloat16(res - __bfloat162float(h));
    }
}

// ---------------------------------------------------------------------------
// Launch
// ---------------------------------------------------------------------------
extern "C" void kernel_launch(void* const* d_in, const int* in_sizes, int n_in,
                              void* d_out, int out_size) {
    const float* x      = (const float*)d_in[0];
    const float* gamma1 = (const float*)d_in[1];
    const float* beta1  = (const float*)d_in[2];
    const float* W1     = (const float*)d_in[3];
    const float* b1     = (const float*)d_in[4];
    const float* W2     = (const float*)d_in[5];
    const float* b2     = (const float*)d_in[6];
    const float* gamma2 = (const float*)d_in[7];
    const float* beta2  = (const float*)d_in[8];
    float* out = (float*)d_out;

    float *scores, *a, *h, *f2;
    bf16 *Phi, *Plo, *xhi, *xlo, *xThi, *xTlo, *hhi, *hlo, *f1hi, *f1lo;
    bf16 *w1thi, *w1tlo, *w2thi, *w2tlo;
    cudaGetSymbolAddress((void**)&scores, g_scores);
    cudaGetSymbolAddress((void**)&Phi, g_Phi);
    cudaGetSymbolAddress((void**)&Plo, g_Plo);
    cudaGetSymbolAddress((void**)&xhi, g_xhi);
    cudaGetSymbolAddress((void**)&xlo, g_xlo);
    cudaGetSymbolAddress((void**)&xThi, g_xThi);
    cudaGetSymbolAddress((void**)&xTlo, g_xTlo);
    cudaGetSymbolAddress((void**)&a, g_a);
    cudaGetSymbolAddress((void**)&h, g_h);
    cudaGetSymbolAddress((void**)&hhi, g_hhi);
    cudaGetSymbolAddress((void**)&hlo, g_hlo);
    cudaGetSymbolAddress((void**)&f1hi, g_f1hi);
    cudaGetSymbolAddress((void**)&f1lo, g_f1lo);
    cudaGetSymbolAddress((void**)&f2, g_f2);
    cudaGetSymbolAddress((void**)&w1thi, g_w1thi);
    cudaGetSymbolAddress((void**)&w1tlo, g_w1tlo);
    cudaGetSymbolAddress((void**)&w2thi, g_w2thi);
    cudaGetSymbolAddress((void**)&w2tlo, g_w2tlo);

    const int SMEM = 2 * Bb;   // 131072
    cudaFuncSetAttribute(gemm_mma<0>, cudaFuncAttributeMaxDynamicSharedMemorySize, SMEM);
    cudaFuncSetAttribute(gemm_mma<1>, cudaFuncAttributeMaxDynamicSharedMemorySize, SMEM);
    cudaFuncSetAttribute(gemm_mma<2>, cudaFuncAttributeMaxDynamicSharedMemorySize, SMEM);
    cudaFuncSetAttribute(gemm_mma<3>, cudaFuncAttributeMaxDynamicSharedMemorySize, SMEM);

    const int rows = BB * SS;

    // conversions
    split_f32<<<(BB * SS * DD + 255) / 256, 256>>>(x, xhi, xlo, (size_t)BB * SS * DD);
    transpose_split<<<dim3(DD / 32, SS / 32, BB), dim3(32, 8)>>>(
        x, xThi, xTlo, SS, DD, (size_t)SS * DD, (size_t)SS * DD);
    transpose_split<<<dim3(HH / 32, DD / 32, 1), dim3(32, 8)>>>(
        W1, w1thi, w1tlo, DD, HH, 0, 0);
    transpose_split<<<dim3(DD / 32, HH / 32, 1), dim3(32, 8)>>>(
        W2, w2thi, w2tlo, HH, DD, 0, 0);

    // 1) scores = SCALE * x x^T
    gemm_mma<0><<<dim3(SS / 128, SS / 128, BB), 256, SMEM>>>(
        xhi, xlo, xhi, xlo, scores, nullptr, nullptr, nullptr,
        SS, SS, DD, (size_t)SS * DD, (size_t)SS * DD, (size_t)SS * SS);

    // 2) softmax -> P hi/lo
    softmax_rows<<<rows, 256>>>(scores, Phi, Plo);

    // 3) a = P @ x  (B = x^T, [N,K] layout)
    gemm_mma<1><<<dim3(DD / 128, SS / 128, BB), 256, SMEM>>>(
        Phi, Plo, xThi, xTlo, a, nullptr, nullptr, nullptr,
        SS, DD, SS, (size_t)SS * SS, (size_t)SS * DD, (size_t)SS * DD);

    // 4) h = LN(a + x), also emit h hi/lo
    add_ln_split<<<rows, 256>>>(a, x, gamma1, beta1, h, hhi, hlo);

    // 5) f1 = relu(h @ W1 + b1) -> bf16 hi/lo
    gemm_mma<2><<<dim3(HH / 128, rows / 128, 1), 256, SMEM>>>(
        hhi, hlo, w1thi, w1tlo, nullptr, f1hi, f1lo, b1,
        rows, HH, DD, 0, 0, 0);

    // 6) f2 = f1 @ W2 + b2
    gemm_mma<3><<<dim3(DD / 128, rows / 128, 1), 256, SMEM>>>(
        f1hi, f1lo, w2thi, w2tlo, f2, nullptr, nullptr, b2,
        rows, DD, HH, 0, 0, 0);

    // 7) out = LN(f2 + h)
    add_ln_split<<<rows, 256>>>(f2, h, gamma2, beta2, out, nullptr, nullptr);
}

// round 5
// speedup vs baseline: 4.4804x; 1.4079x over previous
#include <cuda_runtime.h>
#include <cuda_bf16.h>
#include <cstdint>
#include <math.h>

#define BB 4
#define SS 4096
#define DD 256
#define HH 1024
#define SCALE 0.1767766952966369f   // 32^-0.5

typedef __nv_bfloat16 bf16;

// ---------------------------------------------------------------------------
// Scratch (__device__ globals; no cudaMalloc allowed)
// ---------------------------------------------------------------------------
__device__ bf16  g_xhi[(size_t)BB * SS * DD];
__device__ bf16  g_xlo[(size_t)BB * SS * DD];
__device__ float g_a[(size_t)BB * SS * DD];
__device__ float g_h[(size_t)BB * SS * DD];
__device__ bf16  g_hhi[(size_t)BB * SS * DD];
__device__ bf16  g_hlo[(size_t)BB * SS * DD];
__device__ bf16  g_f1hi[(size_t)BB * SS * HH];
__device__ bf16  g_f1lo[(size_t)BB * SS * HH];
__device__ float g_f2[(size_t)BB * SS * DD];
__device__ bf16  g_w1thi[(size_t)HH * DD];           // W1^T [H,D]
__device__ bf16  g_w1tlo[(size_t)HH * DD];
__device__ bf16  g_w2thi[(size_t)DD * HH];           // W2^T [D,H]
__device__ bf16  g_w2tlo[(size_t)DD * HH];

// ---------------------------------------------------------------------------
// Helpers (baseline PTX only: cp.async, ldmatrix, mma.sync)
// ---------------------------------------------------------------------------
__device__ __forceinline__ uint32_t smem_u32(const void* p) {
    uint32_t a;
    asm("{ .reg .u64 t; cvta.to.shared.u64 t, %1; cvt.u32.u64 %0, t; }" : "=r"(a) : "l"(p));
    return a;
}
__device__ __forceinline__ void cpa16(uint32_t d, const void* g) {
    asm volatile("cp.async.cg.shared.global [%0], [%1], 16;" :: "r"(d), "l"(g) : "memory");
}
__device__ __forceinline__ uint32_t swz(uint32_t off) { return off ^ ((off >> 3) & 0x70); }

// Swizzle for 512B rows (256 bf16): XOR 16B-chunk index low bits with row&7.
__device__ __forceinline__ uint32_t SWX(int row, int c) {
    return (uint32_t)(row * 512 + ((c ^ (row & 7)) << 4));
}

__device__ __forceinline__ void ldsm4(uint32_t& r0, uint32_t& r1, uint32_t& r2, uint32_t& r3,
                                      uint32_t addr) {
    asm volatile("ldmatrix.sync.aligned.m8n8.x4.shared.b16 {%0,%1,%2,%3}, [%4];"
        : "=r"(r0), "=r"(r1), "=r"(r2), "=r"(r3) : "r"(addr));
}
__device__ __forceinline__ void ldsm4t(uint32_t& r0, uint32_t& r1, uint32_t& r2, uint32_t& r3,
                                       uint32_t addr) {
    asm volatile("ldmatrix.sync.aligned.m8n8.x4.trans.shared.b16 {%0,%1,%2,%3}, [%4];"
        : "=r"(r0), "=r"(r1), "=r"(r2), "=r"(r3) : "r"(addr));
}
__device__ __forceinline__ void mma_bf16(float* d, uint32_t a0, uint32_t a1, uint32_t a2,
                                         uint32_t a3, uint32_t b0, uint32_t b1) {
    asm volatile("mma.sync.aligned.m16n8k16.row.col.f32.bf16.bf16.f32 "
        "{%0,%1,%2,%3}, {%4,%5,%6,%7}, {%8,%9}, {%0,%1,%2,%3};"
        : "+f"(d[0]), "+f"(d[1]), "+f"(d[2]), "+f"(d[3])
        : "r"(a0), "r"(a1), "r"(a2), "r"(a3), "r"(b0), "r"(b1));
}
__device__ __forceinline__ uint32_t packbf(float a, float b) {
    __nv_bfloat162 h = __float22bfloat162_rn(make_float2(a, b));
    return *(uint32_t*)&h;
}

// ---------------------------------------------------------------------------
// Flash attention: out[b, q, :] = softmax(scale * x_q . x_k) @ x
// Block: 128 query rows, 8 warps (16 rows each). Key tiles of 32, double buf.
// Q hi+lo resident in smem (3-term scores); P & V hi-only for PV.
// smem: Qhi 64K | Qlo 64K | KV buf0 (Khi 16K, Klo 16K) | KV buf1
// ---------------------------------------------------------------------------
#define FA_SMEM (131072 + 2 * 32768)

__global__ void __launch_bounds__(256, 1) flash_attn(
    const bf16* __restrict__ xhi, const bf16* __restrict__ xlo,
    float* __restrict__ out)
{
    extern __shared__ char smem[];
    const uint32_t sb = smem_u32(smem);
    const int tid = threadIdx.x, wid = tid >> 5, lane = tid & 31;
    const int m0 = blockIdx.x * 128;
    const int bz = blockIdx.y;
    const bf16* qh = xhi + ((size_t)bz * SS + m0) * DD;
    const bf16* ql = xlo + ((size_t)bz * SS + m0) * DD;
    const bf16* kh_all = xhi + (size_t)bz * SS * DD;
    const bf16* kl_all = xlo + (size_t)bz * SS * DD;
    const uint32_t KVB = sb + 131072;

    // Load Q (128 rows x 512B, hi+lo)
    #pragma unroll
    for (int i = 0; i < 16; i++) {
        int j = tid + i * 256;
        int row = j >> 5, c = j & 31;
        uint32_t d = sb + SWX(row, c);
        cpa16(d,         qh + row * DD + c * 8);
        cpa16(d + 65536, ql + row * DD + c * 8);
    }
    asm volatile("cp.async.commit_group;" ::: "memory");

    auto load_kv = [&](int t) {
        const uint32_t b = KVB + (t & 1) * 32768;
        const bf16* kh = kh_all + (size_t)t * 32 * DD;
        const bf16* kl = kl_all + (size_t)t * 32 * DD;
        #pragma unroll
        for (int i = 0; i < 4; i++) {
            int j = tid + i * 256;
            int row = j >> 5, c = j & 31;
            uint32_t d = SWX(row, c);
            cpa16(b + d,         kh + row * DD + c * 8);
            cpa16(b + 16384 + d, kl + row * DD + c * 8);
        }
        asm volatile("cp.async.commit_group;" ::: "memory");
    };

    load_kv(0);

    float O[32][4];
    #pragma unroll
    for (int n = 0; n < 32; n++)
        #pragma unroll
        for (int q = 0; q < 4; q++) O[n][q] = 0.0f;
    float m0r = -INFINITY, m1r = -INFINITY, l0 = 0.0f, l1 = 0.0f;

    const int qrow = wid * 16 + (lane & 15);
    const int qc_h = lane >> 4;
    const int krow = ((lane >> 4) << 3) + (lane & 7);
    const int kc_h = (lane >> 3) & 1;
    const int vrow = ((lane >> 3) & 1) * 8 + (lane & 7);

    const int T = SS / 32;   // 128
    for (int t = 0; t < T; t++) {
        if (t + 1 < T) {
            load_kv(t + 1);
            asm volatile("cp.async.wait_group 1;" ::: "memory");
        } else {
            asm volatile("cp.async.wait_group 0;" ::: "memory");
        }
        __syncthreads();
        const uint32_t kb = KVB + (t & 1) * 32768;

        // ---- S = scale * Q K^T (3-term split) ----
        float sa[4][4];
        #pragma unroll
        for (int j = 0; j < 4; j++)
            #pragma unroll
            for (int q = 0; q < 4; q++) sa[j][q] = 0.0f;

        #pragma unroll
        for (int s = 0; s < 16; s++) {
            uint32_t ah[4], al[4], bh[8], bl[8];
            uint32_t qa = sb + SWX(qrow, 2 * s + qc_h);
            ldsm4(ah[0], ah[1], ah[2], ah[3], qa);
            ldsm4(al[0], al[1], al[2], al[3], qa + 65536);
            uint32_t ka  = kb + SWX(krow,      2 * s + kc_h);
            uint32_t ka2 = kb + SWX(krow + 16, 2 * s + kc_h);
            ldsm4(bh[0], bh[1], bh[2], bh[3], ka);
            ldsm4(bh[4], bh[5], bh[6], bh[7], ka2);
            ldsm4(bl[0], bl[1], bl[2], bl[3], ka + 16384);
            ldsm4(bl[4], bl[5], bl[6], bl[7], ka2 + 16384);
            #pragma unroll
            for (int j = 0; j < 4; j++) {
                mma_bf16(sa[j], ah[0], ah[1], ah[2], ah[3], bh[2 * j], bh[2 * j + 1]);
                mma_bf16(sa[j], ah[0], ah[1], ah[2], ah[3], bl[2 * j], bl[2 * j + 1]);
                mma_bf16(sa[j], al[0], al[1], al[2], al[3], bh[2 * j], bh[2 * j + 1]);
            }
        }
        #pragma unroll
        for (int j = 0; j < 4; j++)
            #pragma unroll
            for (int q = 0; q < 4; q++) sa[j][q] *= SCALE;

        // ---- online softmax ----
        float mx0 = -INFINITY, mx1 = -INFINITY;
        #pragma unroll
        for (int j = 0; j < 4; j++) {
            mx0 = fmaxf(mx0, fmaxf(sa[j][0], sa[j][1]));
            mx1 = fmaxf(mx1, fmaxf(sa[j][2], sa[j][3]));
        }
        mx0 = fmaxf(mx0, __shfl_xor_sync(0xffffffffu, mx0, 1));
        mx0 = fmaxf(mx0, __shfl_xor_sync(0xffffffffu, mx0, 2));
        mx1 = fmaxf(mx1, __shfl_xor_sync(0xffffffffu, mx1, 1));
        mx1 = fmaxf(mx1, __shfl_xor_sync(0xffffffffu, mx1, 2));
        float mn0 = fmaxf(m0r, mx0), mn1 = fmaxf(m1r, mx1);
        float sc0 = __expf(m0r - mn0), sc1 = __expf(m1r - mn1);
        m0r = mn0; m1r = mn1;

        float p[4][4];
        float ts0 = 0.0f, ts1 = 0.0f;
        #pragma unroll
        for (int j = 0; j < 4; j++) {
            p[j][0] = __expf(sa[j][0] - mn0);
            p[j][1] = __expf(sa[j][1] - mn0);
            p[j][2] = __expf(sa[j][2] - mn1);
            p[j][3] = __expf(sa[j][3] - mn1);
            ts0 += p[j][0] + p[j][1];
            ts1 += p[j][2] + p[j][3];
        }
        ts0 += __shfl_xor_sync(0xffffffffu, ts0, 1);
        ts0 += __shfl_xor_sync(0xffffffffu, ts0, 2);
        ts1 += __shfl_xor_sync(0xffffffffu, ts1, 1);
        ts1 += __shfl_xor_sync(0xffffffffu, ts1, 2);
        l0 = l0 * sc0 + ts0;
        l1 = l1 * sc1 + ts1;
        if (sc0 != 1.0f || sc1 != 1.0f) {
            #pragma unroll
            for (int n = 0; n < 32; n++) {
                O[n][0] *= sc0; O[n][1] *= sc0;
                O[n][2] *= sc1; O[n][3] *= sc1;
            }
        }

        // ---- P fragments ----
        uint32_t pa[2][4];
        #pragma unroll
        for (int ks = 0; ks < 2; ks++) {
            int j0 = 2 * ks, j1 = 2 * ks + 1;
            pa[ks][0] = packbf(p[j0][0], p[j0][1]);
            pa[ks][1] = packbf(p[j0][2], p[j0][3]);
            pa[ks][2] = packbf(p[j1][0], p[j1][1]);
            pa[ks][3] = packbf(p[j1][2], p[j1][3]);
        }

        // ---- O += P @ V  (V = Khi tile via ldmatrix.trans) ----
        #pragma unroll
        for (int ks = 0; ks < 2; ks++) {
            #pragma unroll
            for (int g = 0; g < 16; g++) {
                uint32_t v0, v1, v2, v3;
                ldsm4t(v0, v1, v2, v3, kb + SWX(ks * 16 + vrow, 2 * g + (lane >> 4)));
                mma_bf16(O[2 * g],     pa[ks][0], pa[ks][1], pa[ks][2], pa[ks][3], v0, v1);
                mma_bf16(O[2 * g + 1], pa[ks][0], pa[ks][1], pa[ks][2], pa[ks][3], v2, v3);
            }
        }
        __syncthreads();
    }

    // ---- epilogue ----
    const float i0 = 1.0f / l0, i1 = 1.0f / l1;
    float* op = out + ((size_t)bz * SS + m0 + wid * 16) * DD;
    const int r0 = lane >> 2, cq = (lane & 3) * 2;
    #pragma unroll
    for (int n = 0; n < 32; n++) {
        int col = n * 8 + cq;
        *(float2*)(op + (size_t)r0 * DD + col)       = make_float2(O[n][0] * i0, O[n][1] * i0);
        *(float2*)(op + (size_t)(r0 + 8) * DD + col) = make_float2(O[n][2] * i1, O[n][3] * i1);
    }
}

// ---------------------------------------------------------------------------
// Split-bf16 mma.sync GEMM (FFN): C[M,N] = A[M,K] * B[N,K]^T
// MODE 2: (Chi,Clo) bf16 = split(relu(acc + bias))   MODE 3: C fp32 = acc + bias
// ---------------------------------------------------------------------------
#define Bb 65536
template <int MODE>
__global__ void __launch_bounds__(256, 1) gemm_mma(
    const bf16* __restrict__ Ahi_, const bf16* __restrict__ Alo_,
    const bf16* __restrict__ Bhi_, const bf16* __restrict__ Blo_,
    float* __restrict__ C, bf16* __restrict__ Chi, bf16* __restrict__ Clo,
    const float* __restrict__ bias,
    int M, int N, int K, size_t sA, size_t sB, size_t sC)
{
    extern __shared__ char smem[];
    const uint32_t sb = smem_u32(smem);
    const int tid = threadIdx.x, wid = tid >> 5, lane = tid & 31;
    const int bz = blockIdx.z;
    const int m0 = blockIdx.y * 128, n0 = blockIdx.x * 128;
    const bf16* Ahi = Ahi_ + sA * bz;
    const bf16* Alo = Alo_ + sA * bz;
    const bf16* Bhi = Bhi_ + sB * bz;
    const bf16* Blo = Blo_ + sB * bz;

    const int wm = wid & 1;
    const int wn = wid >> 1;
    const int a_row = lane & 15, a_kh = lane >> 4;
    const int b_roff = ((lane >> 4) & 1) * 8 + (lane & 7), b_kh = (lane >> 3) & 1;

    float acc[4][4][4];
    #pragma unroll
    for (int i = 0; i < 4; i++)
        #pragma unroll
        for (int j = 0; j < 4; j++)
            #pragma unroll
            for (int q = 0; q < 4; q++) acc[i][j][q] = 0.0f;

    const int KT = K >> 6;

    auto load_tile = [&](int kt) {
        const uint32_t tb = sb + (kt & 1) * Bb;
        const int k0 = kt << 6;
        #pragma unroll
        for (int t = 0; t < 4; t++) {
            int id = tid + t * 256;
            int row = id >> 3, ch = id & 7;
            uint32_t so = swz((uint32_t)(row * 128 + ch * 16));
            const size_t ga = (size_t)(m0 + row) * K + k0 + ch * 8;
            const size_t gb = (size_t)(n0 + row) * K + k0 + ch * 8;
            cpa16(tb + so,         Ahi + ga);
            cpa16(tb + 16384 + so, Alo + ga);
            cpa16(tb + 32768 + so, Bhi + gb);
            cpa16(tb + 49152 + so, Blo + gb);
        }
        asm volatile("cp.async.commit_group;" ::: "memory");
    };

    load_tile(0);

    for (int kt = 0; kt < KT; kt++) {
        if (kt + 1 < KT) {
            load_tile(kt + 1);
            asm volatile("cp.async.wait_group 1;" ::: "memory");
        } else {
            asm volatile("cp.async.wait_group 0;" ::: "memory");
        }
        __syncthreads();

        const uint32_t tb = sb + (kt & 1) * Bb;
        #pragma unroll
        for (int s = 0; s < 4; s++) {
            uint32_t ah[4][4], al[4][4];
            #pragma unroll
            for (int i = 0; i < 4; i++) {
                uint32_t off = swz((uint32_t)((wm * 64 + i * 16 + a_row) * 128 +
                                              (s * 2 + a_kh) * 16));
                ldsm4(ah[i][0], ah[i][1], ah[i][2], ah[i][3], tb + off);
                ldsm4(al[i][0], al[i][1], al[i][2], al[i][3], tb + 16384 + off);
            }
            uint32_t bh[4][2], bl[4][2];
            #pragma unroll
            for (int jj = 0; jj < 2; jj++) {
                uint32_t off = swz((uint32_t)((wn * 32 + jj * 16 + b_roff) * 128 +
                                              (s * 2 + b_kh) * 16));
                ldsm4(bh[2 * jj][0], bh[2 * jj][1], bh[2 * jj + 1][0], bh[2 * jj + 1][1],
                      tb + 32768 + off);
                ldsm4(bl[2 * jj][0], bl[2 * jj][1], bl[2 * jj + 1][0], bl[2 * jj + 1][1],
                      tb + 49152 + off);
            }
            #pragma unroll
            for (int i = 0; i < 4; i++)
                #pragma unroll
                for (int j = 0; j < 4; j++) {
                    mma_bf16(acc[i][j], ah[i][0], ah[i][1], ah[i][2], ah[i][3],
                             bh[j][0], bh[j][1]);
                    mma_bf16(acc[i][j], ah[i][0], ah[i][1], ah[i][2], ah[i][3],
                             bl[j][0], bl[j][1]);
                    mma_bf16(acc[i][j], al[i][0], al[i][1], al[i][2], al[i][3],
                             bh[j][0], bh[j][1]);
                }
        }
        __syncthreads();
    }

    const int g = lane >> 2, cq = (lane & 3) * 2;
    #pragma unroll
    for (int i = 0; i < 4; i++) {
        #pragma unroll
        for (int j = 0; j < 4; j++) {
            const int row = m0 + wm * 64 + i * 16 + g;
            const int col = n0 + wn * 32 + j * 8 + cq;
            float v0 = acc[i][j][0], v1 = acc[i][j][1];
            float v2 = acc[i][j][2], v3 = acc[i][j][3];
            const float bv0 = bias[col], bv1 = bias[col + 1];
            v0 += bv0; v1 += bv1; v2 += bv0; v3 += bv1;
            size_t i0 = sC * bz + (size_t)row * N + col;
            size_t i1 = sC * bz + (size_t)(row + 8) * N + col;
            if (MODE == 2) {
                v0 = fmaxf(v0, 0.f); v1 = fmaxf(v1, 0.f);
                v2 = fmaxf(v2, 0.f); v3 = fmaxf(v3, 0.f);
                bf16 h0 = __float2bfloat16(v0), h1 = __float2bfloat16(v1);
                bf16 h2 = __float2bfloat16(v2), h3 = __float2bfloat16(v3);
                *(__nv_bfloat162*)(Chi + i0) = {h0, h1};
                *(__nv_bfloat162*)(Chi + i1) = {h2, h3};
                *(__nv_bfloat162*)(Clo + i0) =
                    {__float2bfloat16(v0 - __bfloat162float(h0)),
                     __float2bfloat16(v1 - __bfloat162float(h1))};
                *(__nv_bfloat162*)(Clo + i1) =
                    {__float2bfloat16(v2 - __bfloat162float(h2)),
                     __float2bfloat16(v3 - __bfloat162float(h3))};
            } else {
                *(float2*)(C + i0) = {v0, v1};
                *(float2*)(C + i1) = {v2, v3};
            }
        }
    }
}

// ---------------------------------------------------------------------------
// Elementwise / conversion kernels
// ---------------------------------------------------------------------------
__global__ void split_f32(const float* __restrict__ in, bf16* __restrict__ hi,
                          bf16* __restrict__ lo, size_t n) {
    size_t i = (size_t)blockIdx.x * blockDim.x + threadIdx.x;
    if (i < n) {
        float v = in[i];
        bf16 h = __float2bfloat16(v);
        hi[i] = h;
        lo[i] = __float2bfloat16(v - __bfloat162float(h));
    }
}

__global__ void transpose_split(const float* __restrict__ in, bf16* __restrict__ ohi,
                                bf16* __restrict__ olo, int R, int C) {
    __shared__ float t[32][33];
    int c = blockIdx.x * 32 + threadIdx.x;
    #pragma unroll
    for (int i = 0; i < 4; i++) {
        int r = blockIdx.y * 32 + threadIdx.y + i * 8;
        if (r < R && c < C) t[threadIdx.y + i * 8][threadIdx.x] = in[(size_t)r * C + c];
    }
    __syncthreads();
    int rr = blockIdx.y * 32 + threadIdx.x;
    #pragma unroll
    for (int i = 0; i < 4; i++) {
        int cc = blockIdx.x * 32 + threadIdx.y + i * 8;
        if (rr < R && cc < C) {
            float v = t[threadIdx.x][threadIdx.y + i * 8];
            bf16 h = __float2bfloat16(v);
            size_t idx = (size_t)cc * R + rr;
            ohi[idx] = h;
            olo[idx] = __float2bfloat16(v - __bfloat162float(h));
        }
    }
}

__global__ void add_ln_split(const float* __restrict__ a, const float* __restrict__ r,
                             const float* __restrict__ g, const float* __restrict__ be,
                             float* __restrict__ out, bf16* __restrict__ ohi,
                             bf16* __restrict__ olo) {
    const size_t row = blockIdx.x;
    const int t = threadIdx.x;
    const size_t idx = row * DD + t;
    const float v = a[idx] + r[idx];
    __shared__ float sm[8];

    float s = v;
    #pragma unroll
    for (int o = 16; o > 0; o >>= 1) s += __shfl_xor_sync(0xffffffffu, s, o);
    if ((t & 31) == 0) sm[t >> 5] = s;
    __syncthreads();
    if (t < 32) {
        float z = (t < 8) ? sm[t] : 0.f;
        #pragma unroll
        for (int o = 4; o > 0; o >>= 1) z += __shfl_xor_sync(0xffffffffu, z, o);
        if (t == 0) sm[0] = z;
    }
    __syncthreads();
    const float mean = sm[0] * (1.0f / 256.0f);
    __syncthreads();

    const float d = v - mean;
    float q = d * d;
    #pragma unroll
    for (int o = 16; o > 0; o >>= 1) q += __shfl_xor_sync(0xffffffffu, q, o);
    if ((t & 31) == 0) sm[t >> 5] = q;
    __syncthreads();
    if (t < 32) {
        float z = (t < 8) ? sm[t] : 0.f;
        #pragma unroll
        for (int o = 4; o > 0; o >>= 1) z += __shfl_xor_sync(0xffffffffu, z, o);
        if (t == 0) sm[0] = z;
    }
    __syncthreads();
    const float var = sm[0] * (1.0f / 256.0f);
    const float res = d * rsqrtf(var + 1e-5f) * g[t] + be[t];
    out[idx] = res;
    if (ohi) {
        bf16 h = __float2bfloat16(res);
        ohi[idx] = h;
        olo[idx] = __float2bfloat16(res - __bfloat162float(h));
    }
}

// ---------------------------------------------------------------------------
// Launch
// ---------------------------------------------------------------------------
extern "C" void kernel_launch(void* const* d_in, const int* in_sizes, int n_in,
                              void* d_out, int out_size) {
    const float* x      = (const float*)d_in[0];
    const float* gamma1 = (const float*)d_in[1];
    const float* beta1  = (const float*)d_in[2];
    const float* W1     = (const float*)d_in[3];
    const float* b1     = (const float*)d_in[4];
    const float* W2     = (const float*)d_in[5];
    const float* b2     = (const float*)d_in[6];
    const float* gamma2 = (const float*)d_in[7];
    const float* beta2  = (const float*)d_in[8];
    float* out = (float*)d_out;

    float *a, *h, *f2;
    bf16 *xhi, *xlo, *hhi, *hlo, *f1hi, *f1lo;
    bf16 *w1thi, *w1tlo, *w2thi, *w2tlo;
    cudaGetSymbolAddress((void**)&xhi, g_xhi);
    cudaGetSymbolAddress((void**)&xlo, g_xlo);
    cudaGetSymbolAddress((void**)&a, g_a);
    cudaGetSymbolAddress((void**)&h, g_h);
    cudaGetSymbolAddress((void**)&hhi, g_hhi);
    cudaGetSymbolAddress((void**)&hlo, g_hlo);
    cudaGetSymbolAddress((void**)&f1hi, g_f1hi);
    cudaGetSymbolAddress((void**)&f1lo, g_f1lo);
    cudaGetSymbolAddress((void**)&f2, g_f2);
    cudaGetSymbolAddress((void**)&w1thi, g_w1thi);
    cudaGetSymbolAddress((void**)&w1tlo, g_w1tlo);
    cudaGetSymbolAddress((void**)&w2thi, g_w2thi);
    cudaGetSymbolAddress((void**)&w2tlo, g_w2tlo);

    const int SMEM = 2 * Bb;
    cudaFuncSetAttribute(gemm_mma<2>, cudaFuncAttributeMaxDynamicSharedMemorySize, SMEM);
    cudaFuncSetAttribute(gemm_mma<3>, cudaFuncAttributeMaxDynamicSharedMemorySize, SMEM);
    cudaFuncSetAttribute(flash_attn, cudaFuncAttributeMaxDynamicSharedMemorySize, FA_SMEM);

    const int rows = BB * SS;

    // conversions
    split_f32<<<(BB * SS * DD + 255) / 256, 256>>>(x, xhi, xlo, (size_t)BB * SS * DD);
    transpose_split<<<dim3(HH / 32, DD / 32), dim3(32, 8)>>>(W1, w1thi, w1tlo, DD, HH);
    transpose_split<<<dim3(DD / 32, HH / 32), dim3(32, 8)>>>(W2, w2thi, w2tlo, HH, DD);

    // 1-3) fused attention: a = softmax(scale * x x^T) x
    flash_attn<<<dim3(SS / 128, BB), 256, FA_SMEM>>>(xhi, xlo, a);

    // 4) h = LN(a + x), also emit h hi/lo
    add_ln_split<<<rows, 256>>>(a, x, gamma1, beta1, h, hhi, hlo);

    // 5) f1 = relu(h @ W1 + b1) -> bf16 hi/lo
    gemm_mma<2><<<dim3(HH / 128, rows / 128, 1), 256, SMEM>>>(
        hhi, hlo, w1thi, w1tlo, nullptr, f1hi, f1lo, b1,
        rows, HH, DD, 0, 0, 0);

    // 6) f2 = f1 @ W2 + b2
    gemm_mma<3><<<dim3(DD / 128, rows / 128, 1), 256, SMEM>>>(
        f1hi, f1lo, w2thi, w2tlo, f2, nullptr, nullptr, b2,
        rows, DD, HH, 0, 0, 0);

    // 7) out = LN(f2 + h)
    add_ln_split<<<rows, 256>>>(f2, h, gamma2, beta2, out, nullptr, nullptr);
}

// round 6
// speedup vs baseline: 4.9963x; 1.1151x over previous
#include <cuda_runtime.h>
#include <cuda_fp16.h>
#include <cstdint>
#include <math.h>

#define BB 4
#define SS 4096
#define DD 256
#define HH 1024
#define SCALE 0.1767766952966369f   // 32^-0.5

// ---------------------------------------------------------------------------
// Scratch (__device__ globals; no cudaMalloc allowed)
// ---------------------------------------------------------------------------
__device__ __half g_xhi[(size_t)BB * SS * DD];
__device__ __half g_xlo[(size_t)BB * SS * DD];
__device__ float  g_a[(size_t)BB * SS * DD];
__device__ float  g_h[(size_t)BB * SS * DD];
__device__ __half g_hf[(size_t)BB * SS * DD];
__device__ __half g_f1f[(size_t)BB * SS * HH];
__device__ float  g_f2[(size_t)BB * SS * DD];
__device__ __half g_w1thi[(size_t)HH * DD];          // W1^T [H,D]
__device__ __half g_w1tlo[(size_t)HH * DD];
__device__ __half g_w2thi[(size_t)DD * HH];          // W2^T [D,H]
__device__ __half g_w2tlo[(size_t)DD * HH];

// ---------------------------------------------------------------------------
// Helpers (baseline PTX only: cp.async, ldmatrix, mma.sync)
// ---------------------------------------------------------------------------
__device__ __forceinline__ uint32_t smem_u32(const void* p) {
    uint32_t a;
    asm("{ .reg .u64 t; cvta.to.shared.u64 t, %1; cvt.u32.u64 %0, t; }" : "=r"(a) : "l"(p));
    return a;
}
__device__ __forceinline__ void cpa16(uint32_t d, const void* g) {
    asm volatile("cp.async.cg.shared.global [%0], [%1], 16;" :: "r"(d), "l"(g) : "memory");
}
__device__ __forceinline__ uint32_t swz(uint32_t off) { return off ^ ((off >> 3) & 0x70); }

// Swizzle for 512B rows (256 fp16): XOR 16B-chunk index low bits with row&7.
__device__ __forceinline__ uint32_t SWX(int row, int c) {
    return (uint32_t)(row * 512 + ((c ^ (row & 7)) << 4));
}

__device__ __forceinline__ void ldsm4(uint32_t& r0, uint32_t& r1, uint32_t& r2, uint32_t& r3,
                                      uint32_t addr) {
    asm volatile("ldmatrix.sync.aligned.m8n8.x4.shared.b16 {%0,%1,%2,%3}, [%4];"
        : "=r"(r0), "=r"(r1), "=r"(r2), "=r"(r3) : "r"(addr));
}
__device__ __forceinline__ void ldsm4t(uint32_t& r0, uint32_t& r1, uint32_t& r2, uint32_t& r3,
                                       uint32_t addr) {
    asm volatile("ldmatrix.sync.aligned.m8n8.x4.trans.shared.b16 {%0,%1,%2,%3}, [%4];"
        : "=r"(r0), "=r"(r1), "=r"(r2), "=r"(r3) : "r"(addr));
}
__device__ __forceinline__ void mma_f16(float* d, uint32_t a0, uint32_t a1, uint32_t a2,
                                        uint32_t a3, uint32_t b0, uint32_t b1) {
    asm volatile("mma.sync.aligned.m16n8k16.row.col.f32.f16.f16.f32 "
        "{%0,%1,%2,%3}, {%4,%5,%6,%7}, {%8,%9}, {%0,%1,%2,%3};"
        : "+f"(d[0]), "+f"(d[1]), "+f"(d[2]), "+f"(d[3])
        : "r"(a0), "r"(a1), "r"(a2), "r"(a3), "r"(b0), "r"(b1));
}
__device__ __forceinline__ uint32_t packh(float a, float b) {
    __half2 h = __floats2half2_rn(a, b);
    return *(uint32_t*)&h;
}

// ---------------------------------------------------------------------------
// Flash attention (fp16): a[b,q,:] = softmax(scale * x_q . x_k) @ x
// CTA: 64 query rows, 128 threads (4 warps x 16 rows). 2 CTAs/SM.
// Q hi+lo resident (64K); single-buffered 32-key K hi/lo tile (32K). 96K smem.
// Scores: 3-term split (hi*hi + hi*lo + lo*hi). PV: 1-term fp16.
// ---------------------------------------------------------------------------
#define FA_SMEM 98304

__global__ void __launch_bounds__(128, 2) flash_attn(
    const __half* __restrict__ xhi, const __half* __restrict__ xlo,
    float* __restrict__ out)
{
    extern __shared__ char smem[];
    const uint32_t sb = smem_u32(smem);
    const int tid = threadIdx.x, wid = tid >> 5, lane = tid & 31;
    const int m0 = blockIdx.x * 64;
    const int bz = blockIdx.y;
    const __half* qh = xhi + ((size_t)bz * SS + m0) * DD;
    const __half* ql = xlo + ((size_t)bz * SS + m0) * DD;
    const __half* kh_all = xhi + (size_t)bz * SS * DD;
    const __half* kl_all = xlo + (size_t)bz * SS * DD;
    const uint32_t KVB = sb + 65536;

    // Load Q (64 rows x 512B, hi+lo)
    #pragma unroll
    for (int i = 0; i < 16; i++) {
        int j = tid + i * 128;
        int row = j >> 5, c = j & 31;
        uint32_t d = sb + SWX(row, c);
        cpa16(d,         qh + row * DD + c * 8);
        cpa16(d + 32768, ql + row * DD + c * 8);
    }
    asm volatile("cp.async.commit_group;" ::: "memory");

    auto load_kv = [&](int t) {
        const __half* kh = kh_all + (size_t)t * 32 * DD;
        const __half* kl = kl_all + (size_t)t * 32 * DD;
        #pragma unroll
        for (int i = 0; i < 8; i++) {
            int j = tid + i * 128;
            int row = j >> 5, c = j & 31;
            uint32_t d = KVB + SWX(row, c);
            cpa16(d,         kh + row * DD + c * 8);
            cpa16(d + 16384, kl + row * DD + c * 8);
        }
        asm volatile("cp.async.commit_group;" ::: "memory");
    };

    load_kv(0);

    float O[32][4];
    #pragma unroll
    for (int n = 0; n < 32; n++)
        #pragma unroll
        for (int q = 0; q < 4; q++) O[n][q] = 0.0f;
    float m0r = -INFINITY, m1r = -INFINITY, l0 = 0.0f, l1 = 0.0f;

    const int qrow = wid * 16 + (lane & 15);
    const int qc_h = lane >> 4;
    const int krow = ((lane >> 4) << 3) + (lane & 7);
    const int kc_h = (lane >> 3) & 1;
    const int vrow = ((lane >> 3) & 1) * 8 + (lane & 7);

    const int T = SS / 32;   // 128
    for (int t = 0; t < T; t++) {
        asm volatile("cp.async.wait_group 0;" ::: "memory");
        __syncthreads();
        const uint32_t kb = KVB;

        // ---- S = scale * Q K^T (3-term split) ----
        float sa[4][4];
        #pragma unroll
        for (int j = 0; j < 4; j++)
            #pragma unroll
            for (int q = 0; q < 4; q++) sa[j][q] = 0.0f;

        #pragma unroll
        for (int s = 0; s < 16; s++) {
            uint32_t ah[4], al[4], bh[8], bl[8];
            uint32_t qa = sb + SWX(qrow, 2 * s + qc_h);
            ldsm4(ah[0], ah[1], ah[2], ah[3], qa);
            ldsm4(al[0], al[1], al[2], al[3], qa + 32768);
            uint32_t ka  = kb + SWX(krow,      2 * s + kc_h);
            uint32_t ka2 = kb + SWX(krow + 16, 2 * s + kc_h);
            ldsm4(bh[0], bh[1], bh[2], bh[3], ka);
            ldsm4(bh[4], bh[5], bh[6], bh[7], ka2);
            ldsm4(bl[0], bl[1], bl[2], bl[3], ka + 16384);
            ldsm4(bl[4], bl[5], bl[6], bl[7], ka2 + 16384);
            #pragma unroll
            for (int j = 0; j < 4; j++) {
                mma_f16(sa[j], ah[0], ah[1], ah[2], ah[3], bh[2 * j], bh[2 * j + 1]);
                mma_f16(sa[j], ah[0], ah[1], ah[2], ah[3], bl[2 * j], bl[2 * j + 1]);
                mma_f16(sa[j], al[0], al[1], al[2], al[3], bh[2 * j], bh[2 * j + 1]);
            }
        }
        #pragma unroll
        for (int j = 0; j < 4; j++)
            #pragma unroll
            for (int q = 0; q < 4; q++) sa[j][q] *= SCALE;

        // ---- online softmax (rows lane>>2 and +8; quads share a row) ----
        float mx0 = -INFINITY, mx1 = -INFINITY;
        #pragma unroll
        for (int j = 0; j < 4; j++) {
            mx0 = fmaxf(mx0, fmaxf(sa[j][0], sa[j][1]));
            mx1 = fmaxf(mx1, fmaxf(sa[j][2], sa[j][3]));
        }
        mx0 = fmaxf(mx0, __shfl_xor_sync(0xffffffffu, mx0, 1));
        mx0 = fmaxf(mx0, __shfl_xor_sync(0xffffffffu, mx0, 2));
        mx1 = fmaxf(mx1, __shfl_xor_sync(0xffffffffu, mx1, 1));
        mx1 = fmaxf(mx1, __shfl_xor_sync(0xffffffffu, mx1, 2));
        float mn0 = fmaxf(m0r, mx0), mn1 = fmaxf(m1r, mx1);
        float sc0 = __expf(m0r - mn0), sc1 = __expf(m1r - mn1);
        m0r = mn0; m1r = mn1;

        float p[4][4];
        float ts0 = 0.0f, ts1 = 0.0f;
        #pragma unroll
        for (int j = 0; j < 4; j++) {
            p[j][0] = __expf(sa[j][0] - mn0);
            p[j][1] = __expf(sa[j][1] - mn0);
            p[j][2] = __expf(sa[j][2] - mn1);
            p[j][3] = __expf(sa[j][3] - mn1);
            ts0 += p[j][0] + p[j][1];
            ts1 += p[j][2] + p[j][3];
        }
        ts0 += __shfl_xor_sync(0xffffffffu, ts0, 1);
        ts0 += __shfl_xor_sync(0xffffffffu, ts0, 2);
        ts1 += __shfl_xor_sync(0xffffffffu, ts1, 1);
        ts1 += __shfl_xor_sync(0xffffffffu, ts1, 2);
        l0 = l0 * sc0 + ts0;
        l1 = l1 * sc1 + ts1;
        if (sc0 != 1.0f || sc1 != 1.0f) {
            #pragma unroll
            for (int n = 0; n < 32; n++) {
                O[n][0] *= sc0; O[n][1] *= sc0;
                O[n][2] *= sc1; O[n][3] *= sc1;
            }
        }

        // ---- P fragments (fp16) ----
        uint32_t pa[2][4];
        #pragma unroll
        for (int ks = 0; ks < 2; ks++) {
            int j0 = 2 * ks, j1 = 2 * ks + 1;
            pa[ks][0] = packh(p[j0][0], p[j0][1]);
            pa[ks][1] = packh(p[j0][2], p[j0][3]);
            pa[ks][2] = packh(p[j1][0], p[j1][1]);
            pa[ks][3] = packh(p[j1][2], p[j1][3]);
        }

        // ---- O += P @ V  (V = Khi tile via ldmatrix.trans) ----
        #pragma unroll
        for (int ks = 0; ks < 2; ks++) {
            #pragma unroll
            for (int g = 0; g < 16; g++) {
                uint32_t v0, v1, v2, v3;
                ldsm4t(v0, v1, v2, v3, kb + SWX(ks * 16 + vrow, 2 * g + (lane >> 4)));
                mma_f16(O[2 * g],     pa[ks][0], pa[ks][1], pa[ks][2], pa[ks][3], v0, v1);
                mma_f16(O[2 * g + 1], pa[ks][0], pa[ks][1], pa[ks][2], pa[ks][3], v2, v3);
            }
        }
        __syncthreads();
        if (t + 1 < T) load_kv(t + 1);
    }

    // ---- epilogue ----
    const float i0 = 1.0f / l0, i1 = 1.0f / l1;
    float* op = out + ((size_t)bz * SS + m0 + wid * 16) * DD;
    const int r0 = lane >> 2, cq = (lane & 3) * 2;
    #pragma unroll
    for (int n = 0; n < 32; n++) {
        int col = n * 8 + cq;
        *(float2*)(op + (size_t)r0 * DD + col)       = make_float2(O[n][0] * i0, O[n][1] * i0);
        *(float2*)(op + (size_t)(r0 + 8) * DD + col) = make_float2(O[n][2] * i1, O[n][3] * i1);
    }
}

// ---------------------------------------------------------------------------
// FFN GEMM (fp16, 2-term): C[M,N] = A[M,K] * (Bhi+Blo)[N,K]^T
// A single fp16 (exactness not needed: weights carry the split).
// MODE 2: Cf f16 = relu(acc + bias)      MODE 3: C fp32 = acc + bias
// Block 128x128, K-tile 64, 8 warps (2x4), double-buffered.
// ---------------------------------------------------------------------------
#define Bb 49152   // per-buffer: A 16K | Bhi 16K | Blo 16K
template <int MODE>
__global__ void __launch_bounds__(256, 1) gemm_ffn(
    const __half* __restrict__ A, const __half* __restrict__ Bhi,
    const __half* __restrict__ Blo,
    float* __restrict__ C, __half* __restrict__ Cf,
    const float* __restrict__ bias, int M, int N, int K)
{
    extern __shared__ char smem[];
    const uint32_t sb = smem_u32(smem);
    const int tid = threadIdx.x, wid = tid >> 5, lane = tid & 31;
    const int m0 = blockIdx.y * 128, n0 = blockIdx.x * 128;

    const int wm = wid & 1;
    const int wn = wid >> 1;
    const int a_row = lane & 15, a_kh = lane >> 4;
    const int b_roff = ((lane >> 4) & 1) * 8 + (lane & 7), b_kh = (lane >> 3) & 1;

    float acc[4][4][4];
    #pragma unroll
    for (int i = 0; i < 4; i++)
        #pragma unroll
        for (int j = 0; j < 4; j++)
            #pragma unroll
            for (int q = 0; q < 4; q++) acc[i][j][q] = 0.0f;

    const int KT = K >> 6;

    auto load_tile = [&](int kt) {
        const uint32_t tb = sb + (kt & 1) * Bb;
        const int k0 = kt << 6;
        #pragma unroll
        for (int t = 0; t < 4; t++) {
            int id = tid + t * 256;
            int row = id >> 3, ch = id & 7;
            uint32_t so = swz((uint32_t)(row * 128 + ch * 16));
            cpa16(tb + so,         A   + (size_t)(m0 + row) * K + k0 + ch * 8);
            cpa16(tb + 16384 + so, Bhi + (size_t)(n0 + row) * K + k0 + ch * 8);
            cpa16(tb + 32768 + so, Blo + (size_t)(n0 + row) * K + k0 + ch * 8);
        }
        asm volatile("cp.async.commit_group;" ::: "memory");
    };

    load_tile(0);

    for (int kt = 0; kt < KT; kt++) {
        if (kt + 1 < KT) {
            load_tile(kt + 1);
            asm volatile("cp.async.wait_group 1;" ::: "memory");
        } else {
            asm volatile("cp.async.wait_group 0;" ::: "memory");
        }
        __syncthreads();

        const uint32_t tb = sb + (kt & 1) * Bb;
        #pragma unroll
        for (int s = 0; s < 4; s++) {
            uint32_t av[4][4];
            #pragma unroll
            for (int i = 0; i < 4; i++) {
                uint32_t off = swz((uint32_t)((wm * 64 + i * 16 + a_row) * 128 +
                                              (s * 2 + a_kh) * 16));
                ldsm4(av[i][0], av[i][1], av[i][2], av[i][3], tb + off);
            }
            uint32_t bh[4][2], bl[4][2];
            #pragma unroll
            for (int jj = 0; jj < 2; jj++) {
                uint32_t off = swz((uint32_t)((wn * 32 + jj * 16 + b_roff) * 128 +
                                              (s * 2 + b_kh) * 16));
                ldsm4(bh[2 * jj][0], bh[2 * jj][1], bh[2 * jj + 1][0], bh[2 * jj + 1][1],
                      tb + 16384 + off);
                ldsm4(bl[2 * jj][0], bl[2 * jj][1], bl[2 * jj + 1][0], bl[2 * jj + 1][1],
                      tb + 32768 + off);
            }
            #pragma unroll
            for (int i = 0; i < 4; i++)
                #pragma unroll
                for (int j = 0; j < 4; j++) {
                    mma_f16(acc[i][j], av[i][0], av[i][1], av[i][2], av[i][3],
                            bh[j][0], bh[j][1]);
                    mma_f16(acc[i][j], av[i][0], av[i][1], av[i][2], av[i][3],
                            bl[j][0], bl[j][1]);
                }
        }
        __syncthreads();
    }

    const int g = lane >> 2, cq = (lane & 3) * 2;
    #pragma unroll
    for (int i = 0; i < 4; i++) {
        #pragma unroll
        for (int j = 0; j < 4; j++) {
            const int row = m0 + wm * 64 + i * 16 + g;
            const int col = n0 + wn * 32 + j * 8 + cq;
            float v0 = acc[i][j][0], v1 = acc[i][j][1];
            float v2 = acc[i][j][2], v3 = acc[i][j][3];
            const float bv0 = bias[col], bv1 = bias[col + 1];
            v0 += bv0; v1 += bv1; v2 += bv0; v3 += bv1;
            size_t i0 = (size_t)row * N + col;
            size_t i1 = (size_t)(row + 8) * N + col;
            if (MODE == 2) {
                v0 = fmaxf(v0, 0.f); v1 = fmaxf(v1, 0.f);
                v2 = fmaxf(v2, 0.f); v3 = fmaxf(v3, 0.f);
                *(__half2*)(Cf + i0) = __floats2half2_rn(v0, v1);
                *(__half2*)(Cf + i1) = __floats2half2_rn(v2, v3);
            } else {
                *(float2*)(C + i0) = {v0, v1};
                *(float2*)(C + i1) = {v2, v3};
            }
        }
    }
}

// ---------------------------------------------------------------------------
// Elementwise / conversion kernels
// ---------------------------------------------------------------------------
__global__ void split_f16(const float* __restrict__ in, __half* __restrict__ hi,
                          __half* __restrict__ lo, size_t n) {
    size_t i = (size_t)blockIdx.x * blockDim.x + threadIdx.x;
    if (i < n) {
        float v = in[i];
        __half h = __float2half_rn(v);
        hi[i] = h;
        lo[i] = __float2half_rn(v - __half2float(h));
    }
}

__global__ void transpose_split_f16(const float* __restrict__ in,
                                    __half* __restrict__ ohi, __half* __restrict__ olo,
                                    int R, int C) {
    __shared__ float t[32][33];
    int c = blockIdx.x * 32 + threadIdx.x;
    #pragma unroll
    for (int i = 0; i < 4; i++) {
        int r = blockIdx.y * 32 + threadIdx.y + i * 8;
        if (r < R && c < C) t[threadIdx.y + i * 8][threadIdx.x] = in[(size_t)r * C + c];
    }
    __syncthreads();
    int rr = blockIdx.y * 32 + threadIdx.x;
    #pragma unroll
    for (int i = 0; i < 4; i++) {
        int cc = blockIdx.x * 32 + threadIdx.y + i * 8;
        if (rr < R && cc < C) {
            float v = t[threadIdx.x][threadIdx.y + i * 8];
            __half h = __float2half_rn(v);
            size_t idx = (size_t)cc * R + rr;
            ohi[idx] = h;
            olo[idx] = __float2half_rn(v - __half2float(h));
        }
    }
}

__global__ void add_ln(const float* __restrict__ a, const float* __restrict__ r,
                       const float* __restrict__ g, const float* __restrict__ be,
                       float* __restrict__ out, __half* __restrict__ of) {
    const size_t row = blockIdx.x;
    const int t = threadIdx.x;
    const size_t idx = row * DD + t;
    const float v = a[idx] + r[idx];
    __shared__ float sm[8];

    float s = v;
    #pragma unroll
    for (int o = 16; o > 0; o >>= 1) s += __shfl_xor_sync(0xffffffffu, s, o);
    if ((t & 31) == 0) sm[t >> 5] = s;
    __syncthreads();
    if (t < 32) {
        float z = (t < 8) ? sm[t] : 0.f;
        #pragma unroll
        for (int o = 4; o > 0; o >>= 1) z += __shfl_xor_sync(0xffffffffu, z, o);
        if (t == 0) sm[0] = z;
    }
    __syncthreads();
    const float mean = sm[0] * (1.0f / 256.0f);
    __syncthreads();

    const float d = v - mean;
    float q = d * d;
    #pragma unroll
    for (int o = 16; o > 0; o >>= 1) q += __shfl_xor_sync(0xffffffffu, q, o);
    if ((t & 31) == 0) sm[t >> 5] = q;
    __syncthreads();
    if (t < 32) {
        float z = (t < 8) ? sm[t] : 0.f;
        #pragma unroll
        for (int o = 4; o > 0; o >>= 1) z += __shfl_xor_sync(0xffffffffu, z, o);
        if (t == 0) sm[0] = z;
    }
    __syncthreads();
    const float var = sm[0] * (1.0f / 256.0f);
    const float res = d * rsqrtf(var + 1e-5f) * g[t] + be[t];
    out[idx] = res;
    if (of) of[idx] = __float2half_rn(res);
}

// ---------------------------------------------------------------------------
// Launch
// ---------------------------------------------------------------------------
extern "C" void kernel_launch(void* const* d_in, const int* in_sizes, int n_in,
                              void* d_out, int out_size) {
    const float* x      = (const float*)d_in[0];
    const float* gamma1 = (const float*)d_in[1];
    const float* beta1  = (const float*)d_in[2];
    const float* W1     = (const float*)d_in[3];
    const float* b1     = (const float*)d_in[4];
    const float* W2     = (const float*)d_in[5];
    const float* b2     = (const float*)d_in[6];
    const float* gamma2 = (const float*)d_in[7];
    const float* beta2  = (const float*)d_in[8];
    float* out = (float*)d_out;

    float *a, *h, *f2;
    __half *xhi, *xlo, *hf, *f1f, *w1thi, *w1tlo, *w2thi, *w2tlo;
    cudaGetSymbolAddress((void**)&xhi, g_xhi);
    cudaGetSymbolAddress((void**)&xlo, g_xlo);
    cudaGetSymbolAddress((void**)&a, g_a);
    cudaGetSymbolAddress((void**)&h, g_h);
    cudaGetSymbolAddress((void**)&hf, g_hf);
    cudaGetSymbolAddress((void**)&f1f, g_f1f);
    cudaGetSymbolAddress((void**)&f2, g_f2);
    cudaGetSymbolAddress((void**)&w1thi, g_w1thi);
    cudaGetSymbolAddress((void**)&w1tlo, g_w1tlo);
    cudaGetSymbolAddress((void**)&w2thi, g_w2thi);
    cudaGetSymbolAddress((void**)&w2tlo, g_w2tlo);

    const int SMEM = 2 * Bb;   // 98304
    cudaFuncSetAttribute(gemm_ffn<2>, cudaFuncAttributeMaxDynamicSharedMemorySize, SMEM);
    cudaFuncSetAttribute(gemm_ffn<3>, cudaFuncAttributeMaxDynamicSharedMemorySize, SMEM);
    cudaFuncSetAttribute(flash_attn, cudaFuncAttributeMaxDynamicSharedMemorySize, FA_SMEM);

    const int rows = BB * SS;

    // conversions
    split_f16<<<(BB * SS * DD + 255) / 256, 256>>>(x, xhi, xlo, (size_t)BB * SS * DD);
    transpose_split_f16<<<dim3(HH / 32, DD / 32), dim3(32, 8)>>>(W1, w1thi, w1tlo, DD, HH);
    transpose_split_f16<<<dim3(DD / 32, HH / 32), dim3(32, 8)>>>(W2, w2thi, w2tlo, HH, DD);

    // 1-3) fused attention: a = softmax(scale * x x^T) x
    flash_attn<<<dim3(SS / 64, BB), 128, FA_SMEM>>>(xhi, xlo, a);

    // 4) h = LN(a + x), also emit h f16
    add_ln<<<rows, 256>>>(a, x, gamma1, beta1, h, hf);

    // 5) f1 = relu(h @ W1 + b1) -> f16
    gemm_ffn<2><<<dim3(HH / 128, rows / 128), 256, SMEM>>>(
        hf, w1thi, w1tlo, nullptr, f1f, b1, rows, HH, DD);

    // 6) f2 = f1 @ W2 + b2
    gemm_ffn<3><<<dim3(DD / 128, rows / 128), 256, SMEM>>>(
        f1f, w2thi, w2tlo, f2, nullptr, b2, rows, DD, HH);

    // 7) out = LN(f2 + h)
    add_ln<<<rows, 256>>>(f2, h, gamma2, beta2, out, nullptr);
}

// round 7
// speedup vs baseline: 6.1974x; 1.2404x over previous
#include <cuda_runtime.h>
#include <cuda_fp16.h>
#include <cstdint>
#include <math.h>

#define BB 4
#define SS 4096
#define DD 256
#define HH 1024
#define SCALE 0.1767766952966369f   // 32^-0.5

// ---------------------------------------------------------------------------
// Scratch (__device__ globals; no cudaMalloc allowed)
// ---------------------------------------------------------------------------
__device__ __half g_xhi[(size_t)BB * SS * DD];
__device__ __half g_xlo[(size_t)BB * SS * DD];
__device__ float  g_a[(size_t)BB * SS * DD];
__device__ float  g_h[(size_t)BB * SS * DD];
__device__ __half g_hf[(size_t)BB * SS * DD];
__device__ __half g_f1f[(size_t)BB * SS * HH];
__device__ float  g_f2[(size_t)BB * SS * DD];
__device__ __half g_w1t[(size_t)HH * DD];            // W1^T [H,D] fp16
__device__ __half g_w2t[(size_t)DD * HH];            // W2^T [D,H] fp16

// ---------------------------------------------------------------------------
// Helpers (baseline PTX only: cp.async, ldmatrix, mma.sync)
// ---------------------------------------------------------------------------
__device__ __forceinline__ uint32_t smem_u32(const void* p) {
    uint32_t a;
    asm("{ .reg .u64 t; cvta.to.shared.u64 t, %1; cvt.u32.u64 %0, t; }" : "=r"(a) : "l"(p));
    return a;
}
__device__ __forceinline__ void cpa16(uint32_t d, const void* g) {
    asm volatile("cp.async.cg.shared.global [%0], [%1], 16;" :: "r"(d), "l"(g) : "memory");
}
__device__ __forceinline__ uint32_t swz(uint32_t off) { return off ^ ((off >> 3) & 0x70); }

// Swizzle for 512B rows (256 fp16): XOR 16B-chunk index low bits with row&7.
__device__ __forceinline__ uint32_t SWX(int row, int c) {
    return (uint32_t)(row * 512 + ((c ^ (row & 7)) << 4));
}

__device__ __forceinline__ void ldsm4(uint32_t& r0, uint32_t& r1, uint32_t& r2, uint32_t& r3,
                                      uint32_t addr) {
    asm volatile("ldmatrix.sync.aligned.m8n8.x4.shared.b16 {%0,%1,%2,%3}, [%4];"
        : "=r"(r0), "=r"(r1), "=r"(r2), "=r"(r3) : "r"(addr));
}
__device__ __forceinline__ void ldsm4t(uint32_t& r0, uint32_t& r1, uint32_t& r2, uint32_t& r3,
                                       uint32_t addr) {
    asm volatile("ldmatrix.sync.aligned.m8n8.x4.trans.shared.b16 {%0,%1,%2,%3}, [%4];"
        : "=r"(r0), "=r"(r1), "=r"(r2), "=r"(r3) : "r"(addr));
}
__device__ __forceinline__ void mma_f16(float* d, uint32_t a0, uint32_t a1, uint32_t a2,
                                        uint32_t a3, uint32_t b0, uint32_t b1) {
    asm volatile("mma.sync.aligned.m16n8k16.row.col.f32.f16.f16.f32 "
        "{%0,%1,%2,%3}, {%4,%5,%6,%7}, {%8,%9}, {%0,%1,%2,%3};"
        : "+f"(d[0]), "+f"(d[1]), "+f"(d[2]), "+f"(d[3])
        : "r"(a0), "r"(a1), "r"(a2), "r"(a3), "r"(b0), "r"(b1));
}
__device__ __forceinline__ uint32_t packh(float a, float b) {
    __half2 h = __floats2half2_rn(a, b);
    return *(uint32_t*)&h;
}

// ---------------------------------------------------------------------------
// Flash attention (fp16): a[b,q,:] = softmax(scale * x_q . x_k) @ x
// CTA: 64 query rows, 128 threads (4 warps x 16 rows), 2 CTAs/SM.
// K-tile: 64 keys. Scores 2-term: Qhi*Khi + Qhi*Klo. PV: 1-term fp16 (V=Khi).
// smem: Qhi 32K | Khi 32K | Klo 32K = 96K.
// ---------------------------------------------------------------------------
#define FA_SMEM 98304

__global__ void __launch_bounds__(128, 2) flash_attn(
    const __half* __restrict__ xhi, const __half* __restrict__ xlo,
    float* __restrict__ out)
{
    extern __shared__ char smem[];
    const uint32_t sb = smem_u32(smem);
    const int tid = threadIdx.x, wid = tid >> 5, lane = tid & 31;
    const int m0 = blockIdx.x * 64;
    const int bz = blockIdx.y;
    const __half* qh = xhi + ((size_t)bz * SS + m0) * DD;
    const __half* kh_all = xhi + (size_t)bz * SS * DD;
    const __half* kl_all = xlo + (size_t)bz * SS * DD;
    const uint32_t QH = sb, KH = sb + 32768, KL = sb + 65536;

    // Load Q hi (64 rows x 512B)
    #pragma unroll
    for (int i = 0; i < 16; i++) {
        int j = tid + i * 128;
        int row = j >> 5, c = j & 31;
        cpa16(QH + SWX(row, c), qh + row * DD + c * 8);
    }
    asm volatile("cp.async.commit_group;" ::: "memory");

    auto load_kv = [&](int t) {
        const __half* kh = kh_all + (size_t)t * 64 * DD;
        const __half* kl = kl_all + (size_t)t * 64 * DD;
        #pragma unroll
        for (int i = 0; i < 16; i++) {
            int j = tid + i * 128;
            int row = j >> 5, c = j & 31;
            uint32_t d = SWX(row, c);
            cpa16(KH + d, kh + row * DD + c * 8);
            cpa16(KL + d, kl + row * DD + c * 8);
        }
        asm volatile("cp.async.commit_group;" ::: "memory");
    };

    load_kv(0);

    float O[32][4];
    #pragma unroll
    for (int n = 0; n < 32; n++)
        #pragma unroll
        for (int q = 0; q < 4; q++) O[n][q] = 0.0f;
    float m0r = -INFINITY, m1r = -INFINITY, l0 = 0.0f, l1 = 0.0f;

    const int qrow = wid * 16 + (lane & 15);
    const int qc_h = lane >> 4;
    const int krow = ((lane >> 4) << 3) + (lane & 7);
    const int kc_h = (lane >> 3) & 1;
    const int vrow = ((lane >> 3) & 1) * 8 + (lane & 7);

    const int T = SS / 64;   // 64 key-tiles
    for (int t = 0; t < T; t++) {
        asm volatile("cp.async.wait_group 0;" ::: "memory");
        __syncthreads();

        // ---- S = scale * Q K^T  (2-term: Qhi*Khi + Qhi*Klo) ----
        float sa[8][4];
        #pragma unroll
        for (int j = 0; j < 8; j++)
            #pragma unroll
            for (int q = 0; q < 4; q++) sa[j][q] = 0.0f;

        #pragma unroll
        for (int s = 0; s < 16; s++) {
            uint32_t ah[4], bh[8][2], bl[8][2];
            ldsm4(ah[0], ah[1], ah[2], ah[3], QH + SWX(qrow, 2 * s + qc_h));
            #pragma unroll
            for (int r4 = 0; r4 < 4; r4++) {
                uint32_t off = SWX(krow + 16 * r4, 2 * s + kc_h);
                ldsm4(bh[2 * r4][0], bh[2 * r4][1], bh[2 * r4 + 1][0], bh[2 * r4 + 1][1],
                      KH + off);
                ldsm4(bl[2 * r4][0], bl[2 * r4][1], bl[2 * r4 + 1][0], bl[2 * r4 + 1][1],
                      KL + off);
            }
            #pragma unroll
            for (int j = 0; j < 8; j++) {
                mma_f16(sa[j], ah[0], ah[1], ah[2], ah[3], bh[j][0], bh[j][1]);
                mma_f16(sa[j], ah[0], ah[1], ah[2], ah[3], bl[j][0], bl[j][1]);
            }
        }
        #pragma unroll
        for (int j = 0; j < 8; j++)
            #pragma unroll
            for (int q = 0; q < 4; q++) sa[j][q] *= SCALE;

        // ---- online softmax (rows lane>>2 and +8; quads share a row) ----
        float mx0 = -INFINITY, mx1 = -INFINITY;
        #pragma unroll
        for (int j = 0; j < 8; j++) {
            mx0 = fmaxf(mx0, fmaxf(sa[j][0], sa[j][1]));
            mx1 = fmaxf(mx1, fmaxf(sa[j][2], sa[j][3]));
        }
        mx0 = fmaxf(mx0, __shfl_xor_sync(0xffffffffu, mx0, 1));
        mx0 = fmaxf(mx0, __shfl_xor_sync(0xffffffffu, mx0, 2));
        mx1 = fmaxf(mx1, __shfl_xor_sync(0xffffffffu, mx1, 1));
        mx1 = fmaxf(mx1, __shfl_xor_sync(0xffffffffu, mx1, 2));
        float mn0 = fmaxf(m0r, mx0), mn1 = fmaxf(m1r, mx1);
        float sc0 = __expf(m0r - mn0), sc1 = __expf(m1r - mn1);
        m0r = mn0; m1r = mn1;

        float ts0 = 0.0f, ts1 = 0.0f;
        #pragma unroll
        for (int j = 0; j < 8; j++) {
            sa[j][0] = __expf(sa[j][0] - mn0);
            sa[j][1] = __expf(sa[j][1] - mn0);
            sa[j][2] = __expf(sa[j][2] - mn1);
            sa[j][3] = __expf(sa[j][3] - mn1);
            ts0 += sa[j][0] + sa[j][1];
            ts1 += sa[j][2] + sa[j][3];
        }
        ts0 += __shfl_xor_sync(0xffffffffu, ts0, 1);
        ts0 += __shfl_xor_sync(0xffffffffu, ts0, 2);
        ts1 += __shfl_xor_sync(0xffffffffu, ts1, 1);
        ts1 += __shfl_xor_sync(0xffffffffu, ts1, 2);
        l0 = l0 * sc0 + ts0;
        l1 = l1 * sc1 + ts1;
        if (sc0 != 1.0f || sc1 != 1.0f) {
            #pragma unroll
            for (int n = 0; n < 32; n++) {
                O[n][0] *= sc0; O[n][1] *= sc0;
                O[n][2] *= sc1; O[n][3] *= sc1;
            }
        }

        // ---- P fragments (fp16), 4 k16 chunks over 64 keys ----
        uint32_t pa[4][4];
        #pragma unroll
        for (int ks = 0; ks < 4; ks++) {
            int j0 = 2 * ks, j1 = 2 * ks + 1;
            pa[ks][0] = packh(sa[j0][0], sa[j0][1]);
            pa[ks][1] = packh(sa[j0][2], sa[j0][3]);
            pa[ks][2] = packh(sa[j1][0], sa[j1][1]);
            pa[ks][3] = packh(sa[j1][2], sa[j1][3]);
        }

        // ---- O += P @ V  (V = Khi tile via ldmatrix.trans) ----
        #pragma unroll
        for (int ks = 0; ks < 4; ks++) {
            #pragma unroll
            for (int g = 0; g < 16; g++) {
                uint32_t v0, v1, v2, v3;
                ldsm4t(v0, v1, v2, v3, KH + SWX(ks * 16 + vrow, 2 * g + (lane >> 4)));
                mma_f16(O[2 * g],     pa[ks][0], pa[ks][1], pa[ks][2], pa[ks][3], v0, v1);
                mma_f16(O[2 * g + 1], pa[ks][0], pa[ks][1], pa[ks][2], pa[ks][3], v2, v3);
            }
        }
        __syncthreads();
        if (t + 1 < T) load_kv(t + 1);
    }

    // ---- epilogue ----
    const float i0 = 1.0f / l0, i1 = 1.0f / l1;
    float* op = out + ((size_t)bz * SS + m0 + wid * 16) * DD;
    const int r0 = lane >> 2, cq = (lane & 3) * 2;
    #pragma unroll
    for (int n = 0; n < 32; n++) {
        int col = n * 8 + cq;
        *(float2*)(op + (size_t)r0 * DD + col)       = make_float2(O[n][0] * i0, O[n][1] * i0);
        *(float2*)(op + (size_t)(r0 + 8) * DD + col) = make_float2(O[n][2] * i1, O[n][3] * i1);
    }
}

// ---------------------------------------------------------------------------
// FFN GEMM (fp16, 1-term): C[M,N] = A[M,K] * B[N,K]^T
// MODE 2: Cf f16 = relu(acc + bias)      MODE 3: C fp32 = acc + bias
// Block 128x128, K-tile 64, 8 warps (2x4), double-buffered.
// ---------------------------------------------------------------------------
#define Bb 32768   // per-buffer: A 16K | B 16K
template <int MODE>
__global__ void __launch_bounds__(256, 1) gemm_ffn(
    const __half* __restrict__ A, const __half* __restrict__ B,
    float* __restrict__ C, __half* __restrict__ Cf,
    const float* __restrict__ bias, int M, int N, int K)
{
    extern __shared__ char smem[];
    const uint32_t sb = smem_u32(smem);
    const int tid = threadIdx.x, wid = tid >> 5, lane = tid & 31;
    const int m0 = blockIdx.y * 128, n0 = blockIdx.x * 128;

    const int wm = wid & 1;
    const int wn = wid >> 1;
    const int a_row = lane & 15, a_kh = lane >> 4;
    const int b_roff = ((lane >> 4) & 1) * 8 + (lane & 7), b_kh = (lane >> 3) & 1;

    float acc[4][4][4];
    #pragma unroll
    for (int i = 0; i < 4; i++)
        #pragma unroll
        for (int j = 0; j < 4; j++)
            #pragma unroll
            for (int q = 0; q < 4; q++) acc[i][j][q] = 0.0f;

    const int KT = K >> 6;

    auto load_tile = [&](int kt) {
        const uint32_t tb = sb + (kt & 1) * Bb;
        const int k0 = kt << 6;
        #pragma unroll
        for (int t = 0; t < 4; t++) {
            int id = tid + t * 256;
            int row = id >> 3, ch = id & 7;
            uint32_t so = swz((uint32_t)(row * 128 + ch * 16));
            cpa16(tb + so,         A + (size_t)(m0 + row) * K + k0 + ch * 8);
            cpa16(tb + 16384 + so, B + (size_t)(n0 + row) * K + k0 + ch * 8);
        }
        asm volatile("cp.async.commit_group;" ::: "memory");
    };

    load_tile(0);

    for (int kt = 0; kt < KT; kt++) {
        if (kt + 1 < KT) {
            load_tile(kt + 1);
            asm volatile("cp.async.wait_group 1;" ::: "memory");
        } else {
            asm volatile("cp.async.wait_group 0;" ::: "memory");
        }
        __syncthreads();

        const uint32_t tb = sb + (kt & 1) * Bb;
        #pragma unroll
        for (int s = 0; s < 4; s++) {
            uint32_t av[4][4];
            #pragma unroll
            for (int i = 0; i < 4; i++) {
                uint32_t off = swz((uint32_t)((wm * 64 + i * 16 + a_row) * 128 +
                                              (s * 2 + a_kh) * 16));
                ldsm4(av[i][0], av[i][1], av[i][2], av[i][3], tb + off);
            }
            uint32_t bv[4][2];
            #pragma unroll
            for (int jj = 0; jj < 2; jj++) {
                uint32_t off = swz((uint32_t)((wn * 32 + jj * 16 + b_roff) * 128 +
                                              (s * 2 + b_kh) * 16));
                ldsm4(bv[2 * jj][0], bv[2 * jj][1], bv[2 * jj + 1][0], bv[2 * jj + 1][1],
                      tb + 16384 + off);
            }
            #pragma unroll
            for (int i = 0; i < 4; i++)
                #pragma unroll
                for (int j = 0; j < 4; j++)
                    mma_f16(acc[i][j], av[i][0], av[i][1], av[i][2], av[i][3],
                            bv[j][0], bv[j][1]);
        }
        __syncthreads();
    }

    const int g = lane >> 2, cq = (lane & 3) * 2;
    #pragma unroll
    for (int i = 0; i < 4; i++) {
        #pragma unroll
        for (int j = 0; j < 4; j++) {
            const int row = m0 + wm * 64 + i * 16 + g;
            const int col = n0 + wn * 32 + j * 8 + cq;
            float v0 = acc[i][j][0], v1 = acc[i][j][1];
            float v2 = acc[i][j][2], v3 = acc[i][j][3];
            const float bv0 = bias[col], bv1 = bias[col + 1];
            v0 += bv0; v1 += bv1; v2 += bv0; v3 += bv1;
            size_t i0 = (size_t)row * N + col;
            size_t i1 = (size_t)(row + 8) * N + col;
            if (MODE == 2) {
                v0 = fmaxf(v0, 0.f); v1 = fmaxf(v1, 0.f);
                v2 = fmaxf(v2, 0.f); v3 = fmaxf(v3, 0.f);
                *(__half2*)(Cf + i0) = __floats2half2_rn(v0, v1);
                *(__half2*)(Cf + i1) = __floats2half2_rn(v2, v3);
            } else {
                *(float2*)(C + i0) = {v0, v1};
                *(float2*)(C + i1) = {v2, v3};
            }
        }
    }
}

// ---------------------------------------------------------------------------
// Elementwise / conversion kernels
// ---------------------------------------------------------------------------
__global__ void split_f16(const float* __restrict__ in, __half* __restrict__ hi,
                          __half* __restrict__ lo, size_t n) {
    size_t i = (size_t)blockIdx.x * blockDim.x + threadIdx.x;
    if (i < n) {
        float v = in[i];
        __half h = __float2half_rn(v);
        hi[i] = h;
        lo[i] = __float2half_rn(v - __half2float(h));
    }
}

__global__ void transpose_f16(const float* __restrict__ in, __half* __restrict__ o,
                              int R, int C) {
    __shared__ float t[32][33];
    int c = blockIdx.x * 32 + threadIdx.x;
    #pragma unroll
    for (int i = 0; i < 4; i++) {
        int r = blockIdx.y * 32 + threadIdx.y + i * 8;
        if (r < R && c < C) t[threadIdx.y + i * 8][threadIdx.x] = in[(size_t)r * C + c];
    }
    __syncthreads();
    int rr = blockIdx.y * 32 + threadIdx.x;
    #pragma unroll
    for (int i = 0; i < 4; i++) {
        int cc = blockIdx.x * 32 + threadIdx.y + i * 8;
        if (rr < R && cc < C)
            o[(size_t)cc * R + rr] = __float2half_rn(t[threadIdx.x][threadIdx.y + i * 8]);
    }
}

__global__ void add_ln(const float* __restrict__ a, const float* __restrict__ r,
                       const float* __restrict__ g, const float* __restrict__ be,
                       float* __restrict__ out, __half* __restrict__ of) {
    const size_t row = blockIdx.x;
    const int t = threadIdx.x;
    const size_t idx = row * DD + t;
    const float v = a[idx] + r[idx];
    __shared__ float sm[8];

    float s = v;
    #pragma unroll
    for (int o = 16; o > 0; o >>= 1) s += __shfl_xor_sync(0xffffffffu, s, o);
    if ((t & 31) == 0) sm[t >> 5] = s;
    __syncthreads();
    if (t < 32) {
        float z = (t < 8) ? sm[t] : 0.f;
        #pragma unroll
        for (int o = 4; o > 0; o >>= 1) z += __shfl_xor_sync(0xffffffffu, z, o);
        if (t == 0) sm[0] = z;
    }
    __syncthreads();
    const float mean = sm[0] * (1.0f / 256.0f);
    __syncthreads();

    const float d = v - mean;
    float q = d * d;
    #pragma unroll
    for (int o = 16; o > 0; o >>= 1) q += __shfl_xor_sync(0xffffffffu, q, o);
    if ((t & 31) == 0) sm[t >> 5] = q;
    __syncthreads();
    if (t < 32) {
        float z = (t < 8) ? sm[t] : 0.f;
        #pragma unroll
        for (int o = 4; o > 0; o >>= 1) z += __shfl_xor_sync(0xffffffffu, z, o);
        if (t == 0) sm[0] = z;
    }
    __syncthreads();
    const float var = sm[0] * (1.0f / 256.0f);
    const float res = d * rsqrtf(var + 1e-5f) * g[t] + be[t];
    out[idx] = res;
    if (of) of[idx] = __float2half_rn(res);
}

// ---------------------------------------------------------------------------
// Launch
// ---------------------------------------------------------------------------
extern "C" void kernel_launch(void* const* d_in, const int* in_sizes, int n_in,
                              void* d_out, int out_size) {
    const float* x      = (const float*)d_in[0];
    const float* gamma1 = (const float*)d_in[1];
    const float* beta1  = (const float*)d_in[2];
    const float* W1     = (const float*)d_in[3];
    const float* b1     = (const float*)d_in[4];
    const float* W2     = (const float*)d_in[5];
    const float* b2     = (const float*)d_in[6];
    const float* gamma2 = (const float*)d_in[7];
    const float* beta2  = (const float*)d_in[8];
    float* out = (float*)d_out;

    float *a, *h, *f2;
    __half *xhi, *xlo, *hf, *f1f, *w1t, *w2t;
    cudaGetSymbolAddress((void**)&xhi, g_xhi);
    cudaGetSymbolAddress((void**)&xlo, g_xlo);
    cudaGetSymbolAddress((void**)&a, g_a);
    cudaGetSymbolAddress((void**)&h, g_h);
    cudaGetSymbolAddress((void**)&hf, g_hf);
    cudaGetSymbolAddress((void**)&f1f, g_f1f);
    cudaGetSymbolAddress((void**)&f2, g_f2);
    cudaGetSymbolAddress((void**)&w1t, g_w1t);
    cudaGetSymbolAddress((void**)&w2t, g_w2t);

    const int SMEM = 2 * Bb;   // 65536
    cudaFuncSetAttribute(gemm_ffn<2>, cudaFuncAttributeMaxDynamicSharedMemorySize, SMEM);
    cudaFuncSetAttribute(gemm_ffn<3>, cudaFuncAttributeMaxDynamicSharedMemorySize, SMEM);
    cudaFuncSetAttribute(flash_attn, cudaFuncAttributeMaxDynamicSharedMemorySize, FA_SMEM);

    const int rows = BB * SS;

    // conversions
    split_f16<<<(BB * SS * DD + 255) / 256, 256>>>(x, xhi, xlo, (size_t)BB * SS * DD);
    transpose_f16<<<dim3(HH / 32, DD / 32), dim3(32, 8)>>>(W1, w1t, DD, HH);
    transpose_f16<<<dim3(DD / 32, HH / 32), dim3(32, 8)>>>(W2, w2t, HH, DD);

    // 1-3) fused attention: a = softmax(scale * x x^T) x
    flash_attn<<<dim3(SS / 64, BB), 128, FA_SMEM>>>(xhi, xlo, a);

    // 4) h = LN(a + x), also emit h f16
    add_ln<<<rows, 256>>>(a, x, gamma1, beta1, h, hf);

    // 5) f1 = relu(h @ W1 + b1) -> f16
    gemm_ffn<2><<<dim3(HH / 128, rows / 128), 256, SMEM>>>(
        hf, w1t, nullptr, f1f, b1, rows, HH, DD);

    // 6) f2 = f1 @ W2 + b2
    gemm_ffn<3><<<dim3(DD / 128, rows / 128), 256, SMEM>>>(
        f1f, w2t, f2, nullptr, b2, rows, DD, HH);

    // 7) out = LN(f2 + h)
    add_ln<<<rows, 256>>>(f2, h, gamma2, beta2, out, nullptr);
}